// round 1
// baseline (speedup 1.0000x reference)
#include <cuda_runtime.h>
#include <cuda_bf16.h>

#define D_MODEL 1024
#define NH 16
#define HD 64
#define CHUNK 256
#define WIN 64
#define BATCH 4
#define SEQ 8192
#define NCHUNK (SEQ / CHUNK)
#define ROWS (BATCH * SEQ)

// Scratch (allocation-free rule: use __device__ globals)
__device__ float g_q[ROWS * D_MODEL];
__device__ float g_k[ROWS * D_MODEL];
__device__ float g_v[ROWS * D_MODEL];
__device__ float g_att[ROWS * D_MODEL];

// ---------------------------------------------------------------------------
// fp32 SIMT GEMM: C[M,N] = A[M,K] @ B[K,N], all row-major.
// 128x128 tile, BK=8, 256 threads, 8x8 accumulator per thread.
// M,N,K all divisible by tile dims for our shapes — no bounds checks.
// ---------------------------------------------------------------------------
#define BM 128
#define BN 128
#define BK 8

__global__ __launch_bounds__(256) void sgemm_kernel(
    const float* __restrict__ A, const float* __restrict__ B,
    float* __restrict__ C, int M, int N, int K)
{
    __shared__ float As[BK][BM];   // transposed A tile: As[k][m]
    __shared__ float Bs[BK][BN];

    const int tid = threadIdx.x;
    const int tx = tid & 15;       // 0..15 -> 8 cols each
    const int ty = tid >> 4;       // 0..15 -> 8 rows each
    const int cRow = blockIdx.y * BM;
    const int cCol = blockIdx.x * BN;

    const int arow = tid >> 1;            // 0..127
    const int acol = (tid & 1) << 2;      // 0 or 4
    const int brow = tid >> 5;            // 0..7
    const int bcol = (tid & 31) << 2;     // 0..124

    const float* Aptr = A + (size_t)(cRow + arow) * K + acol;
    const float* Bptr = B + (size_t)brow * N + cCol + bcol;

    float acc[8][8];
    #pragma unroll
    for (int i = 0; i < 8; i++)
        #pragma unroll
        for (int j = 0; j < 8; j++) acc[i][j] = 0.f;

    for (int k0 = 0; k0 < K; k0 += BK) {
        float4 av = *(const float4*)(Aptr + k0);
        As[acol + 0][arow] = av.x;
        As[acol + 1][arow] = av.y;
        As[acol + 2][arow] = av.z;
        As[acol + 3][arow] = av.w;
        float4 bv = *(const float4*)(Bptr + (size_t)k0 * N);
        *(float4*)&Bs[brow][bcol] = bv;
        __syncthreads();

        #pragma unroll
        for (int kk = 0; kk < BK; kk++) {
            float af[8], bf[8];
            #pragma unroll
            for (int i = 0; i < 8; i++) af[i] = As[kk][ty * 8 + i];
            #pragma unroll
            for (int j = 0; j < 8; j++) bf[j] = Bs[kk][tx * 8 + j];
            #pragma unroll
            for (int i = 0; i < 8; i++)
                #pragma unroll
                for (int j = 0; j < 8; j++)
                    acc[i][j] += af[i] * bf[j];
        }
        __syncthreads();
    }

    #pragma unroll
    for (int i = 0; i < 8; i++) {
        float* crow = C + (size_t)(cRow + ty * 8 + i) * N + cCol + tx * 8;
        *(float4*)(crow)     = make_float4(acc[i][0], acc[i][1], acc[i][2], acc[i][3]);
        *(float4*)(crow + 4) = make_float4(acc[i][4], acc[i][5], acc[i][6], acc[i][7]);
    }
}

// ---------------------------------------------------------------------------
// Banded chunk-local attention. One CTA per (b, chunk, head).
// Each query i attends keys j in [max(0, i-64), i] (65 positions max).
// Thread t = query t. k and v staged (sequentially, same buffer) in smem
// with stride 65 (odd -> conflict-free for both row-access patterns).
// smem: buf[256*65] (k, then v, also used to stage q and output) +
//       sc[256*65] (scores -> probs). Total 133,120 B dynamic smem.
// ---------------------------------------------------------------------------
#define ATT_STRIDE 65
#define ATT_SMEM_BYTES (2 * CHUNK * ATT_STRIDE * 4)

__device__ __forceinline__ void load_tile_65(
    float* __restrict__ buf, const float* __restrict__ src, size_t base, int tid)
{
    // 256x64 tile from a D_MODEL-stride matrix into stride-65 smem
    for (int idx = tid; idx < CHUNK * (HD / 4); idx += 256) {
        int r = idx >> 4;
        int c4 = (idx & 15) << 2;
        float4 t = *(const float4*)(src + base + (size_t)r * D_MODEL + c4);
        float* d = buf + r * ATT_STRIDE + c4;
        d[0] = t.x; d[1] = t.y; d[2] = t.z; d[3] = t.w;
    }
}

__global__ __launch_bounds__(256) void attn_kernel(
    const float* __restrict__ q, const float* __restrict__ k,
    const float* __restrict__ v, float* __restrict__ o)
{
    extern __shared__ float smem[];
    float* buf = smem;                       // [CHUNK][65]
    float* sc  = smem + CHUNK * ATT_STRIDE;  // [CHUNK][65]

    const int h = blockIdx.x;
    const int n = blockIdx.y;
    const int b = blockIdx.z;
    const int tid = threadIdx.x;             // query index within chunk

    const size_t base = ((size_t)(b * SEQ + n * CHUNK)) * D_MODEL + h * HD;

    // ---- stage q, pull own row into registers (pre-scaled) ----
    load_tile_65(buf, q, base, tid);
    __syncthreads();
    float qr[HD];
    #pragma unroll
    for (int d = 0; d < HD; d++) qr[d] = buf[tid * ATT_STRIDE + d] * 0.125f;
    __syncthreads();

    // ---- k tile ----
    load_tile_65(buf, k, base, tid);
    __syncthreads();

    // ---- scores over the band ----
    float m = -1e30f;
    #pragma unroll
    for (int jj = 0; jj <= WIN; jj++) {
        int j = tid - WIN + jj;
        float s = -1e30f;
        if (j >= 0) {
            float acc = 0.f;
            const float* kr = buf + j * ATT_STRIDE;
            #pragma unroll
            for (int d = 0; d < HD; d++) acc += qr[d] * kr[d];
            s = acc;
            m = fmaxf(m, s);
        }
        sc[tid * ATT_STRIDE + jj] = s;
    }

    float l = 0.f;
    #pragma unroll
    for (int jj = 0; jj <= WIN; jj++) {
        int j = tid - WIN + jj;
        float p = 0.f;
        if (j >= 0) p = __expf(sc[tid * ATT_STRIDE + jj] - m);
        l += p;
        sc[tid * ATT_STRIDE + jj] = p;
    }
    __syncthreads();

    // ---- v tile (reuse buf) ----
    load_tile_65(buf, v, base, tid);
    __syncthreads();

    // ---- P @ V over the band ----
    float acc[HD];
    #pragma unroll
    for (int d = 0; d < HD; d++) acc[d] = 0.f;
    #pragma unroll
    for (int jj = 0; jj <= WIN; jj++) {
        int j = tid - WIN + jj;
        if (j >= 0) {
            float p = sc[tid * ATT_STRIDE + jj];
            const float* vr = buf + j * ATT_STRIDE;
            #pragma unroll
            for (int d = 0; d < HD; d++) acc[d] += p * vr[d];
        }
    }
    const float rinv = 1.f / l;
    __syncthreads();

    // ---- stage output through smem for coalesced store ----
    #pragma unroll
    for (int d = 0; d < HD; d++) buf[tid * ATT_STRIDE + d] = acc[d] * rinv;
    __syncthreads();
    for (int idx = tid; idx < CHUNK * (HD / 4); idx += 256) {
        int r = idx >> 4;
        int c4 = (idx & 15) << 2;
        const float* s = buf + r * ATT_STRIDE + c4;
        *(float4*)(o + base + (size_t)r * D_MODEL + c4) =
            make_float4(s[0], s[1], s[2], s[3]);
    }
}

// ---------------------------------------------------------------------------
// kernel_launch: 3x GEMM (q,k,v) -> attention -> GEMM (Wo)
// ---------------------------------------------------------------------------
extern "C" void kernel_launch(void* const* d_in, const int* in_sizes, int n_in,
                              void* d_out, int out_size)
{
    const float* x  = (const float*)d_in[0];
    const float* Wq = (const float*)d_in[1];
    const float* Wk = (const float*)d_in[2];
    const float* Wv = (const float*)d_in[3];
    const float* Wo = (const float*)d_in[4];
    float* out = (float*)d_out;

    float *q, *k, *v, *att;
    cudaGetSymbolAddress((void**)&q,   g_q);
    cudaGetSymbolAddress((void**)&k,   g_k);
    cudaGetSymbolAddress((void**)&v,   g_v);
    cudaGetSymbolAddress((void**)&att, g_att);

    cudaFuncSetAttribute(attn_kernel,
                         cudaFuncAttributeMaxDynamicSharedMemorySize,
                         ATT_SMEM_BYTES);

    dim3 gemm_grid(D_MODEL / BN, ROWS / BM);   // (8, 256)
    sgemm_kernel<<<gemm_grid, 256>>>(x, Wq, q, ROWS, D_MODEL, D_MODEL);
    sgemm_kernel<<<gemm_grid, 256>>>(x, Wk, k, ROWS, D_MODEL, D_MODEL);
    sgemm_kernel<<<gemm_grid, 256>>>(x, Wv, v, ROWS, D_MODEL, D_MODEL);

    dim3 attn_grid(NH, NCHUNK, BATCH);         // (16, 32, 4)
    attn_kernel<<<attn_grid, 256, ATT_SMEM_BYTES>>>(q, k, v, att);

    sgemm_kernel<<<gemm_grid, 256>>>(att, Wo, out, ROWS, D_MODEL, D_MODEL);
}

// round 3
// speedup vs baseline: 2.1969x; 2.1969x over previous
#include <cuda_runtime.h>
#include <cuda_bf16.h>
#include <cstdint>

#define D_MODEL 1024
#define NH 16
#define HD 64
#define CHUNK 256
#define WIN 64
#define BATCH 4
#define SEQ 8192
#define NCHUNK (SEQ / CHUNK)
#define ROWS (BATCH * SEQ)

// ---------------- scratch (__device__ globals; no allocs allowed) ----------
__device__ float g_q[ROWS * D_MODEL];
__device__ float g_k[ROWS * D_MODEL];
__device__ float g_v[ROWS * D_MODEL];
__device__ float g_att[ROWS * D_MODEL];
__device__ __nv_bfloat16 g_x_hi[ROWS * D_MODEL];
__device__ __nv_bfloat16 g_x_lo[ROWS * D_MODEL];
__device__ __nv_bfloat16 g_att_hi[ROWS * D_MODEL];
__device__ __nv_bfloat16 g_att_lo[ROWS * D_MODEL];
// 4 transposed weights (q,k,v,o), hi/lo limbs, each [N=1024][K=1024] (K-major)
__device__ __nv_bfloat16 g_wt_hi[4 * D_MODEL * D_MODEL];
__device__ __nv_bfloat16 g_wt_lo[4 * D_MODEL * D_MODEL];

// ---------------------------------------------------------------------------
// helpers
// ---------------------------------------------------------------------------
__device__ __forceinline__ uint32_t smem_u32(const void* p) {
    uint32_t a;
    asm("{ .reg .u64 t; cvta.to.shared.u64 t, %1; cvt.u32.u64 %0, t; }"
        : "=r"(a) : "l"(p));
    return a;
}

__device__ __forceinline__ void cp_async16(uint32_t dst, const void* src) {
    asm volatile("cp.async.cg.shared.global [%0], [%1], 16;"
                 :: "r"(dst), "l"(src) : "memory");
}
__device__ __forceinline__ void cp_commit() {
    asm volatile("cp.async.commit_group;" ::: "memory");
}
__device__ __forceinline__ void cp_wait1() {
    asm volatile("cp.async.wait_group 1;" ::: "memory");
}

__device__ __forceinline__ void ldsm_x4(uint32_t* r, uint32_t addr) {
    asm volatile("ldmatrix.sync.aligned.m8n8.x4.shared.b16 {%0,%1,%2,%3}, [%4];"
                 : "=r"(r[0]), "=r"(r[1]), "=r"(r[2]), "=r"(r[3]) : "r"(addr));
}

__device__ __forceinline__ void mma16816(float* c, const uint32_t* a, const uint32_t* b) {
    asm volatile(
        "mma.sync.aligned.m16n8k16.row.col.f32.bf16.bf16.f32 "
        "{%0,%1,%2,%3}, {%4,%5,%6,%7}, {%8,%9}, {%0,%1,%2,%3};"
        : "+f"(c[0]), "+f"(c[1]), "+f"(c[2]), "+f"(c[3])
        : "r"(a[0]), "r"(a[1]), "r"(a[2]), "r"(a[3]), "r"(b[0]), "r"(b[1]));
}

// tile geometry: 128 rows x 32 bf16 cols = 64B rows, 4x 16B chunks per row
// swizzled 16B-chunk: c' = c ^ ((r>>1)&3)
#define TILE_B 8192
#define STAGE_B (4 * TILE_B)   // Ahi, Alo, Bhi, Blo
#define NSTAGE 3
#define GEMM_SMEM (NSTAGE * STAGE_B)  // 98304
#define KIT 32                 // 1024 / 32

__device__ __forceinline__ uint32_t sw_addr(uint32_t tile_base, int r, int c) {
    return tile_base + r * 64 + ((c ^ ((r >> 1) & 3)) << 4);
}

// ---------------------------------------------------------------------------
// Split fp32 -> bf16 hi/lo limbs
// ---------------------------------------------------------------------------
__global__ __launch_bounds__(256) void split_kernel(
    const float* __restrict__ in, __nv_bfloat16* __restrict__ hi,
    __nv_bfloat16* __restrict__ lo, int n4)
{
    int i = blockIdx.x * blockDim.x + threadIdx.x;
    if (i >= n4) return;
    float4 x = ((const float4*)in)[i];
    float v[4] = {x.x, x.y, x.z, x.w};
    __nv_bfloat16 h[4], l[4];
#pragma unroll
    for (int j = 0; j < 4; j++) {
        h[j] = __float2bfloat16(v[j]);
        l[j] = __float2bfloat16(v[j] - __bfloat162float(h[j]));
    }
    *(uint2*)(hi + 4 * (size_t)i) = *(uint2*)h;
    *(uint2*)(lo + 4 * (size_t)i) = *(uint2*)l;
}

// Weight transpose + split: hiT[n*1024+k] = split(W[k*1024+n])
__global__ __launch_bounds__(256) void wsplit_kernel(
    const float* __restrict__ W, __nv_bfloat16* __restrict__ hiT,
    __nv_bfloat16* __restrict__ loT)
{
    __shared__ float tile[32][33];
    int bx = blockIdx.x * 32, by = blockIdx.y * 32;
    int tx = threadIdx.x, ty = threadIdx.y;  // 32x8
#pragma unroll
    for (int r = ty; r < 32; r += 8)
        tile[r][tx] = W[(size_t)(by + r) * D_MODEL + bx + tx];
    __syncthreads();
#pragma unroll
    for (int r = ty; r < 32; r += 8) {
        float v = tile[tx][r];  // = W[(by+tx)*D + bx+r]
        __nv_bfloat16 h = __float2bfloat16(v);
        size_t o = (size_t)(bx + r) * D_MODEL + by + tx;
        hiT[o] = h;
        loT[o] = __float2bfloat16(v - __bfloat162float(h));
    }
}

// ---------------------------------------------------------------------------
// bf16-split GEMM via mma.sync: C[M,1024] = (Ahi+Alo) @ (Bhi+Blo)^T, fp32 acc
// A: [M][1024] K-major. B: [1024][1024] K-major (pre-transposed weight).
// CTA 128x128, BK=32, 3-stage cp.async pipeline, 8 warps (2m x 4n), each
// warp owns 64x32 via m16n8k16 (4 m-tiles x 4 n-tiles).
// 3 limb passes per k-step: hi*hi, hi*lo, lo*hi.
// ---------------------------------------------------------------------------
__global__ __launch_bounds__(256, 1) void gemm_mma_kernel(
    const __nv_bfloat16* __restrict__ Ahi, const __nv_bfloat16* __restrict__ Alo,
    const __nv_bfloat16* __restrict__ Bhi, const __nv_bfloat16* __restrict__ Blo,
    float* __restrict__ C)
{
    extern __shared__ char smem[];
    const uint32_t sbase = smem_u32(smem);
    const int tid = threadIdx.x;
    const int lane = tid & 31;
    const int wid = tid >> 5;
    const int wm = wid >> 2;        // 0..1
    const int wn = wid & 3;         // 0..3
    const int m0 = blockIdx.y * 128;
    const int n0 = blockIdx.x * 128;

    const __nv_bfloat16* srcs[4] = {Ahi, Alo, Bhi, Blo};

    // load one stage: 4 tiles x 512 chunks of 16B, 8 chunks per thread
    auto load_stage = [&](int stage, int k0) {
        uint32_t sb = sbase + stage * STAGE_B;
#pragma unroll
        for (int t = 0; t < 4; t++) {
            int row0 = (t < 2) ? m0 : n0;
            const __nv_bfloat16* s = srcs[t];
#pragma unroll
            for (int i = 0; i < 2; i++) {
                int cid = tid + i * 256;       // 0..511
                int r = cid >> 2;
                int c = cid & 3;
                const void* g = s + (size_t)(row0 + r) * D_MODEL + k0 + c * 8;
                cp_async16(sw_addr(sb + t * TILE_B, r, c), g);
            }
        }
    };

    float acc[4][4][4];
#pragma unroll
    for (int i = 0; i < 4; i++)
#pragma unroll
        for (int j = 0; j < 4; j++)
#pragma unroll
            for (int e = 0; e < 4; e++) acc[i][j][e] = 0.f;

    load_stage(0, 0);
    cp_commit();
    load_stage(1, 32);
    cp_commit();

    // fragment smem addresses depend only on lane + stage base
    const int a_r = lane & 15;            // row within 16-row tile
    const int a_c = lane >> 4;            // 0/1 chunk
    const int b_r = (lane & 7) + ((lane >> 4) << 3);
    const int b_c = (lane >> 3) & 1;

    for (int it = 0; it < KIT; it++) {
        cp_wait1();
        __syncthreads();
        if (it + 2 < KIT) load_stage((it + 2) % NSTAGE, (it + 2) * 32);
        cp_commit();

        const uint32_t sb = sbase + (it % NSTAGE) * STAGE_B;
        const uint32_t tAhi = sb;
        const uint32_t tAlo = sb + TILE_B;
        const uint32_t tBhi = sb + 2 * TILE_B;
        const uint32_t tBlo = sb + 3 * TILE_B;

#pragma unroll
        for (int ks = 0; ks < 2; ks++) {
            uint32_t a[4][4], bh[4][2], bl[4][2];
            // A_hi fragments: 4 m-tiles
#pragma unroll
            for (int mt = 0; mt < 4; mt++) {
                int r = wm * 64 + mt * 16 + a_r;
                ldsm_x4(a[mt], sw_addr(tAhi, r, ks * 2 + a_c));
            }
            // B_hi fragments: 2 x ldmatrix.x4 cover 4 n-tiles
#pragma unroll
            for (int np = 0; np < 2; np++) {
                uint32_t t4[4];
                int r = wn * 32 + np * 16 + b_r;
                ldsm_x4(t4, sw_addr(tBhi, r, ks * 2 + b_c));
                bh[np * 2][0] = t4[0]; bh[np * 2][1] = t4[1];
                bh[np * 2 + 1][0] = t4[2]; bh[np * 2 + 1][1] = t4[3];
            }
            // pass 1: hi * hi
#pragma unroll
            for (int mt = 0; mt < 4; mt++)
#pragma unroll
                for (int nt = 0; nt < 4; nt++)
                    mma16816(acc[mt][nt], a[mt], bh[nt]);
            // B_lo
#pragma unroll
            for (int np = 0; np < 2; np++) {
                uint32_t t4[4];
                int r = wn * 32 + np * 16 + b_r;
                ldsm_x4(t4, sw_addr(tBlo, r, ks * 2 + b_c));
                bl[np * 2][0] = t4[0]; bl[np * 2][1] = t4[1];
                bl[np * 2 + 1][0] = t4[2]; bl[np * 2 + 1][1] = t4[3];
            }
            // pass 2: hi * lo
#pragma unroll
            for (int mt = 0; mt < 4; mt++)
#pragma unroll
                for (int nt = 0; nt < 4; nt++)
                    mma16816(acc[mt][nt], a[mt], bl[nt]);
            // A_lo (reuse a regs)
#pragma unroll
            for (int mt = 0; mt < 4; mt++) {
                int r = wm * 64 + mt * 16 + a_r;
                ldsm_x4(a[mt], sw_addr(tAlo, r, ks * 2 + a_c));
            }
            // pass 3: lo * hi
#pragma unroll
            for (int mt = 0; mt < 4; mt++)
#pragma unroll
                for (int nt = 0; nt < 4; nt++)
                    mma16816(acc[mt][nt], a[mt], bh[nt]);
        }
        __syncthreads();
    }

    // epilogue: c fragment -> gmem
    const int er = lane >> 2;        // 0..7
    const int ec = (lane & 3) * 2;
#pragma unroll
    for (int mt = 0; mt < 4; mt++) {
#pragma unroll
        for (int nt = 0; nt < 4; nt++) {
            int row = m0 + wm * 64 + mt * 16 + er;
            int col = n0 + wn * 32 + nt * 8 + ec;
            *(float2*)(C + (size_t)row * D_MODEL + col) =
                make_float2(acc[mt][nt][0], acc[mt][nt][1]);
            *(float2*)(C + (size_t)(row + 8) * D_MODEL + col) =
                make_float2(acc[mt][nt][2], acc[mt][nt][3]);
        }
    }
}

// ---------------------------------------------------------------------------
// Banded chunk-local attention (fp32, unchanged from R1)
// ---------------------------------------------------------------------------
#define ATT_STRIDE 65
#define ATT_SMEM_BYTES (2 * CHUNK * ATT_STRIDE * 4)

__device__ __forceinline__ void load_tile_65(
    float* __restrict__ buf, const float* __restrict__ src, size_t base, int tid)
{
    for (int idx = tid; idx < CHUNK * (HD / 4); idx += 256) {
        int r = idx >> 4;
        int c4 = (idx & 15) << 2;
        float4 t = *(const float4*)(src + base + (size_t)r * D_MODEL + c4);
        float* d = buf + r * ATT_STRIDE + c4;
        d[0] = t.x; d[1] = t.y; d[2] = t.z; d[3] = t.w;
    }
}

__global__ __launch_bounds__(256) void attn_kernel(
    const float* __restrict__ q, const float* __restrict__ k,
    const float* __restrict__ v, float* __restrict__ o)
{
    extern __shared__ float fsmem[];
    float* buf = fsmem;
    float* sc  = fsmem + CHUNK * ATT_STRIDE;

    const int h = blockIdx.x;
    const int n = blockIdx.y;
    const int b = blockIdx.z;
    const int tid = threadIdx.x;

    const size_t base = ((size_t)(b * SEQ + n * CHUNK)) * D_MODEL + h * HD;

    load_tile_65(buf, q, base, tid);
    __syncthreads();
    float qr[HD];
#pragma unroll
    for (int d = 0; d < HD; d++) qr[d] = buf[tid * ATT_STRIDE + d] * 0.125f;
    __syncthreads();

    load_tile_65(buf, k, base, tid);
    __syncthreads();

    float m = -1e30f;
#pragma unroll
    for (int jj = 0; jj <= WIN; jj++) {
        int j = tid - WIN + jj;
        float s = -1e30f;
        if (j >= 0) {
            float acc = 0.f;
            const float* kr = buf + j * ATT_STRIDE;
#pragma unroll
            for (int d = 0; d < HD; d++) acc += qr[d] * kr[d];
            s = acc;
            m = fmaxf(m, s);
        }
        sc[tid * ATT_STRIDE + jj] = s;
    }

    float l = 0.f;
#pragma unroll
    for (int jj = 0; jj <= WIN; jj++) {
        int j = tid - WIN + jj;
        float p = 0.f;
        if (j >= 0) p = __expf(sc[tid * ATT_STRIDE + jj] - m);
        l += p;
        sc[tid * ATT_STRIDE + jj] = p;
    }
    __syncthreads();

    load_tile_65(buf, v, base, tid);
    __syncthreads();

    float acc[HD];
#pragma unroll
    for (int d = 0; d < HD; d++) acc[d] = 0.f;
#pragma unroll
    for (int jj = 0; jj <= WIN; jj++) {
        int j = tid - WIN + jj;
        if (j >= 0) {
            float p = sc[tid * ATT_STRIDE + jj];
            const float* vr = buf + j * ATT_STRIDE;
#pragma unroll
            for (int d = 0; d < HD; d++) acc[d] += p * vr[d];
        }
    }
    const float rinv = 1.f / l;
    __syncthreads();

#pragma unroll
    for (int d = 0; d < HD; d++) buf[tid * ATT_STRIDE + d] = acc[d] * rinv;
    __syncthreads();
    for (int idx = tid; idx < CHUNK * (HD / 4); idx += 256) {
        int r = idx >> 4;
        int c4 = (idx & 15) << 2;
        const float* s = buf + r * ATT_STRIDE + c4;
        *(float4*)(o + base + (size_t)r * D_MODEL + c4) =
            make_float4(s[0], s[1], s[2], s[3]);
    }
}

// ---------------------------------------------------------------------------
extern "C" void kernel_launch(void* const* d_in, const int* in_sizes, int n_in,
                              void* d_out, int out_size)
{
    const float* x  = (const float*)d_in[0];
    const float* Wq = (const float*)d_in[1];
    const float* Wk = (const float*)d_in[2];
    const float* Wv = (const float*)d_in[3];
    const float* Wo = (const float*)d_in[4];
    float* out = (float*)d_out;

    float *q, *k, *v, *att;
    __nv_bfloat16 *x_hi, *x_lo, *att_hi, *att_lo, *wt_hi, *wt_lo;
    cudaGetSymbolAddress((void**)&q, g_q);
    cudaGetSymbolAddress((void**)&k, g_k);
    cudaGetSymbolAddress((void**)&v, g_v);
    cudaGetSymbolAddress((void**)&att, g_att);
    cudaGetSymbolAddress((void**)&x_hi, g_x_hi);
    cudaGetSymbolAddress((void**)&x_lo, g_x_lo);
    cudaGetSymbolAddress((void**)&att_hi, g_att_hi);
    cudaGetSymbolAddress((void**)&att_lo, g_att_lo);
    cudaGetSymbolAddress((void**)&wt_hi, g_wt_hi);
    cudaGetSymbolAddress((void**)&wt_lo, g_wt_lo);

    cudaFuncSetAttribute(gemm_mma_kernel,
                         cudaFuncAttributeMaxDynamicSharedMemorySize, GEMM_SMEM);
    cudaFuncSetAttribute(attn_kernel,
                         cudaFuncAttributeMaxDynamicSharedMemorySize, ATT_SMEM_BYTES);

    const size_t DD = (size_t)D_MODEL * D_MODEL;
    const int n4 = ROWS * D_MODEL / 4;

    // conversions
    split_kernel<<<(n4 + 255) / 256, 256>>>(x, x_hi, x_lo, n4);
    dim3 wgrid(32, 32), wblk(32, 8);
    wsplit_kernel<<<wgrid, wblk>>>(Wq, wt_hi + 0 * DD, wt_lo + 0 * DD);
    wsplit_kernel<<<wgrid, wblk>>>(Wk, wt_hi + 1 * DD, wt_lo + 1 * DD);
    wsplit_kernel<<<wgrid, wblk>>>(Wv, wt_hi + 2 * DD, wt_lo + 2 * DD);
    wsplit_kernel<<<wgrid, wblk>>>(Wo, wt_hi + 3 * DD, wt_lo + 3 * DD);

    // QKV projections on tensor cores (mma.sync)
    dim3 gg(D_MODEL / 128, ROWS / 128);   // (8, 256)
    gemm_mma_kernel<<<gg, 256, GEMM_SMEM>>>(x_hi, x_lo, wt_hi + 0 * DD, wt_lo + 0 * DD, q);
    gemm_mma_kernel<<<gg, 256, GEMM_SMEM>>>(x_hi, x_lo, wt_hi + 1 * DD, wt_lo + 1 * DD, k);
    gemm_mma_kernel<<<gg, 256, GEMM_SMEM>>>(x_hi, x_lo, wt_hi + 2 * DD, wt_lo + 2 * DD, v);

    // attention
    dim3 attn_grid(NH, NCHUNK, BATCH);
    attn_kernel<<<attn_grid, 256, ATT_SMEM_BYTES>>>(q, k, v, att);

    // output projection
    split_kernel<<<(n4 + 255) / 256, 256>>>(att, att_hi, att_lo, n4);
    gemm_mma_kernel<<<gg, 256, GEMM_SMEM>>>(att_hi, att_lo, wt_hi + 3 * DD, wt_lo + 3 * DD, out);
}

// round 4
// speedup vs baseline: 2.9495x; 1.3426x over previous
#include <cuda_runtime.h>
#include <cuda_bf16.h>
#include <cstdint>

#define D_MODEL 1024
#define NH 16
#define HD 64
#define CHUNK 256
#define WIN 64
#define BATCH 4
#define SEQ 8192
#define NCHUNK (SEQ / CHUNK)
#define ROWS (BATCH * SEQ)

// ---------------- scratch (__device__ globals; no allocs allowed) ----------
__device__ float g_q[ROWS * D_MODEL];
__device__ float g_k[ROWS * D_MODEL];
__device__ float g_v[ROWS * D_MODEL];
__device__ __nv_bfloat16 g_x_hi[ROWS * D_MODEL];
__device__ __nv_bfloat16 g_x_lo[ROWS * D_MODEL];
__device__ __nv_bfloat16 g_att_hi[ROWS * D_MODEL];
__device__ __nv_bfloat16 g_att_lo[ROWS * D_MODEL];
// 4 transposed weights (q,k,v,o), hi/lo limbs, each [N=1024][K=1024] (K-major)
__device__ __nv_bfloat16 g_wt_hi[4 * D_MODEL * D_MODEL];
__device__ __nv_bfloat16 g_wt_lo[4 * D_MODEL * D_MODEL];

// ---------------------------------------------------------------------------
// helpers
// ---------------------------------------------------------------------------
__device__ __forceinline__ uint32_t smem_u32(const void* p) {
    uint32_t a;
    asm("{ .reg .u64 t; cvta.to.shared.u64 t, %1; cvt.u32.u64 %0, t; }"
        : "=r"(a) : "l"(p));
    return a;
}

__device__ __forceinline__ void cp_async16(uint32_t dst, const void* src) {
    asm volatile("cp.async.cg.shared.global [%0], [%1], 16;"
                 :: "r"(dst), "l"(src) : "memory");
}
__device__ __forceinline__ void cp_commit() {
    asm volatile("cp.async.commit_group;" ::: "memory");
}
__device__ __forceinline__ void cp_wait1() {
    asm volatile("cp.async.wait_group 1;" ::: "memory");
}

__device__ __forceinline__ void ldsm_x4(uint32_t* r, uint32_t addr) {
    asm volatile("ldmatrix.sync.aligned.m8n8.x4.shared.b16 {%0,%1,%2,%3}, [%4];"
                 : "=r"(r[0]), "=r"(r[1]), "=r"(r[2]), "=r"(r[3]) : "r"(addr));
}

__device__ __forceinline__ void mma16816(float* c, const uint32_t* a, const uint32_t* b) {
    asm volatile(
        "mma.sync.aligned.m16n8k16.row.col.f32.bf16.bf16.f32 "
        "{%0,%1,%2,%3}, {%4,%5,%6,%7}, {%8,%9}, {%0,%1,%2,%3};"
        : "+f"(c[0]), "+f"(c[1]), "+f"(c[2]), "+f"(c[3])
        : "r"(a[0]), "r"(a[1]), "r"(a[2]), "r"(a[3]), "r"(b[0]), "r"(b[1]));
}

// tile geometry: 128 rows x 32 bf16 cols = 64B rows, 4x 16B chunks per row
// swizzled 16B-chunk: c' = c ^ ((r>>1)&3)
#define TILE_B 8192
#define STAGE_B (4 * TILE_B)   // Ahi, Alo, Bhi, Blo
#define NSTAGE 3
#define GEMM_SMEM (NSTAGE * STAGE_B)  // 98304
#define KIT 32                 // 1024 / 32

__device__ __forceinline__ uint32_t sw_addr(uint32_t tile_base, int r, int c) {
    return tile_base + r * 64 + ((c ^ ((r >> 1) & 3)) << 4);
}

// ---------------------------------------------------------------------------
// Split fp32 -> bf16 hi/lo limbs
// ---------------------------------------------------------------------------
__global__ __launch_bounds__(256) void split_kernel(
    const float* __restrict__ in, __nv_bfloat16* __restrict__ hi,
    __nv_bfloat16* __restrict__ lo, int n4)
{
    int i = blockIdx.x * blockDim.x + threadIdx.x;
    if (i >= n4) return;
    float4 x = ((const float4*)in)[i];
    float v[4] = {x.x, x.y, x.z, x.w};
    __nv_bfloat16 h[4], l[4];
#pragma unroll
    for (int j = 0; j < 4; j++) {
        h[j] = __float2bfloat16(v[j]);
        l[j] = __float2bfloat16(v[j] - __bfloat162float(h[j]));
    }
    *(uint2*)(hi + 4 * (size_t)i) = *(uint2*)h;
    *(uint2*)(lo + 4 * (size_t)i) = *(uint2*)l;
}

// Weight transpose + split: hiT[n*1024+k] = split(W[k*1024+n])
__global__ __launch_bounds__(256) void wsplit_kernel(
    const float* __restrict__ W, __nv_bfloat16* __restrict__ hiT,
    __nv_bfloat16* __restrict__ loT)
{
    __shared__ float tile[32][33];
    int bx = blockIdx.x * 32, by = blockIdx.y * 32;
    int tx = threadIdx.x, ty = threadIdx.y;  // 32x8
#pragma unroll
    for (int r = ty; r < 32; r += 8)
        tile[r][tx] = W[(size_t)(by + r) * D_MODEL + bx + tx];
    __syncthreads();
#pragma unroll
    for (int r = ty; r < 32; r += 8) {
        float v = tile[tx][r];  // = W[(by+tx)*D + bx+r]
        __nv_bfloat16 h = __float2bfloat16(v);
        size_t o = (size_t)(bx + r) * D_MODEL + by + tx;
        hiT[o] = h;
        loT[o] = __float2bfloat16(v - __bfloat162float(h));
    }
}

// ---------------------------------------------------------------------------
// bf16-split GEMM via mma.sync: C[M,1024] = (Ahi+Alo) @ (Bhi+Blo)^T, fp32 acc
// CTA 128x128, BK=32, 3-stage cp.async pipeline, 8 warps (2m x 4n),
// now 2 CTAs/SM for latency hiding.
// ---------------------------------------------------------------------------
__global__ __launch_bounds__(256, 2) void gemm_mma_kernel(
    const __nv_bfloat16* __restrict__ Ahi, const __nv_bfloat16* __restrict__ Alo,
    const __nv_bfloat16* __restrict__ Bhi, const __nv_bfloat16* __restrict__ Blo,
    float* __restrict__ C)
{
    extern __shared__ char smem[];
    const uint32_t sbase = smem_u32(smem);
    const int tid = threadIdx.x;
    const int lane = tid & 31;
    const int wid = tid >> 5;
    const int wm = wid >> 2;        // 0..1
    const int wn = wid & 3;         // 0..3
    const int m0 = blockIdx.y * 128;
    const int n0 = blockIdx.x * 128;

    const __nv_bfloat16* srcs[4] = {Ahi, Alo, Bhi, Blo};

    auto load_stage = [&](int stage, int k0) {
        uint32_t sb = sbase + stage * STAGE_B;
#pragma unroll
        for (int t = 0; t < 4; t++) {
            int row0 = (t < 2) ? m0 : n0;
            const __nv_bfloat16* s = srcs[t];
#pragma unroll
            for (int i = 0; i < 2; i++) {
                int cid = tid + i * 256;       // 0..511
                int r = cid >> 2;
                int c = cid & 3;
                const void* g = s + (size_t)(row0 + r) * D_MODEL + k0 + c * 8;
                cp_async16(sw_addr(sb + t * TILE_B, r, c), g);
            }
        }
    };

    float acc[4][4][4];
#pragma unroll
    for (int i = 0; i < 4; i++)
#pragma unroll
        for (int j = 0; j < 4; j++)
#pragma unroll
            for (int e = 0; e < 4; e++) acc[i][j][e] = 0.f;

    load_stage(0, 0);
    cp_commit();
    load_stage(1, 32);
    cp_commit();

    const int a_r = lane & 15;
    const int a_c = lane >> 4;
    const int b_r = (lane & 7) + ((lane >> 4) << 3);
    const int b_c = (lane >> 3) & 1;

    for (int it = 0; it < KIT; it++) {
        cp_wait1();
        __syncthreads();
        if (it + 2 < KIT) load_stage((it + 2) % NSTAGE, (it + 2) * 32);
        cp_commit();

        const uint32_t sb = sbase + (it % NSTAGE) * STAGE_B;
        const uint32_t tAhi = sb;
        const uint32_t tAlo = sb + TILE_B;
        const uint32_t tBhi = sb + 2 * TILE_B;
        const uint32_t tBlo = sb + 3 * TILE_B;

#pragma unroll
        for (int ks = 0; ks < 2; ks++) {
            uint32_t a[4][4], bh[4][2], bl[4][2];
#pragma unroll
            for (int mt = 0; mt < 4; mt++) {
                int r = wm * 64 + mt * 16 + a_r;
                ldsm_x4(a[mt], sw_addr(tAhi, r, ks * 2 + a_c));
            }
#pragma unroll
            for (int np = 0; np < 2; np++) {
                uint32_t t4[4];
                int r = wn * 32 + np * 16 + b_r;
                ldsm_x4(t4, sw_addr(tBhi, r, ks * 2 + b_c));
                bh[np * 2][0] = t4[0]; bh[np * 2][1] = t4[1];
                bh[np * 2 + 1][0] = t4[2]; bh[np * 2 + 1][1] = t4[3];
            }
#pragma unroll
            for (int mt = 0; mt < 4; mt++)
#pragma unroll
                for (int nt = 0; nt < 4; nt++)
                    mma16816(acc[mt][nt], a[mt], bh[nt]);
#pragma unroll
            for (int np = 0; np < 2; np++) {
                uint32_t t4[4];
                int r = wn * 32 + np * 16 + b_r;
                ldsm_x4(t4, sw_addr(tBlo, r, ks * 2 + b_c));
                bl[np * 2][0] = t4[0]; bl[np * 2][1] = t4[1];
                bl[np * 2 + 1][0] = t4[2]; bl[np * 2 + 1][1] = t4[3];
            }
#pragma unroll
            for (int mt = 0; mt < 4; mt++)
#pragma unroll
                for (int nt = 0; nt < 4; nt++)
                    mma16816(acc[mt][nt], a[mt], bl[nt]);
#pragma unroll
            for (int mt = 0; mt < 4; mt++) {
                int r = wm * 64 + mt * 16 + a_r;
                ldsm_x4(a[mt], sw_addr(tAlo, r, ks * 2 + a_c));
            }
#pragma unroll
            for (int mt = 0; mt < 4; mt++)
#pragma unroll
                for (int nt = 0; nt < 4; nt++)
                    mma16816(acc[mt][nt], a[mt], bh[nt]);
        }
        __syncthreads();
    }

    const int er = lane >> 2;
    const int ec = (lane & 3) * 2;
#pragma unroll
    for (int mt = 0; mt < 4; mt++) {
#pragma unroll
        for (int nt = 0; nt < 4; nt++) {
            int row = m0 + wm * 64 + mt * 16 + er;
            int col = n0 + wn * 32 + nt * 8 + ec;
            *(float2*)(C + (size_t)row * D_MODEL + col) =
                make_float2(acc[mt][nt][0], acc[mt][nt][1]);
            *(float2*)(C + (size_t)(row + 8) * D_MODEL + col) =
                make_float2(acc[mt][nt][2], acc[mt][nt][3]);
        }
    }
}

// ---------------------------------------------------------------------------
// Banded chunk-local attention, vectorized smem (stride-68 float4, LDS.128),
// fused bf16 hi/lo output split.
// smem: buf[256*68] (k then v, also q staging) + sc[256*65] (scores->probs)
// ---------------------------------------------------------------------------
#define ATT_KS 68
#define ATT_SMEM_BYTES ((CHUNK * ATT_KS + CHUNK * 65) * 4)  // 136192

__device__ __forceinline__ void load_tile68(
    float* __restrict__ buf, const float* __restrict__ src, size_t base, int tid)
{
#pragma unroll
    for (int i = 0; i < 16; i++) {
        int idx = tid + i * 256;
        int r = idx >> 4;
        int c4 = (idx & 15) << 2;
        float4 t = *(const float4*)(src + base + (size_t)r * D_MODEL + c4);
        *(float4*)(buf + r * ATT_KS + c4) = t;
    }
}

__global__ __launch_bounds__(256) void attn_kernel(
    const float* __restrict__ q, const float* __restrict__ k,
    const float* __restrict__ v,
    __nv_bfloat16* __restrict__ ohi, __nv_bfloat16* __restrict__ olo)
{
    extern __shared__ float fsmem[];
    float* buf = fsmem;                      // [256][68]
    float* sc  = fsmem + CHUNK * ATT_KS;     // [256][65]

    const int h = blockIdx.x;
    const int n = blockIdx.y;
    const int b = blockIdx.z;
    const int tid = threadIdx.x;             // query index within chunk

    const size_t base = ((size_t)(b * SEQ + n * CHUNK)) * D_MODEL + h * HD;

    // ---- stage q, pull own row into registers (pre-scaled) ----
    load_tile68(buf, q, base, tid);
    __syncthreads();
    float qr[HD];
#pragma unroll
    for (int d4 = 0; d4 < 16; d4++) {
        float4 t = *(const float4*)(buf + tid * ATT_KS + d4 * 4);
        qr[4 * d4 + 0] = t.x * 0.125f;
        qr[4 * d4 + 1] = t.y * 0.125f;
        qr[4 * d4 + 2] = t.z * 0.125f;
        qr[4 * d4 + 3] = t.w * 0.125f;
    }
    __syncthreads();

    // ---- k tile ----
    load_tile68(buf, k, base, tid);
    __syncthreads();

    // ---- scores over the band (vectorized LDS.128) ----
    float m = -1e30f;
#pragma unroll
    for (int jj = 0; jj <= WIN; jj++) {
        int j = tid - WIN + jj;
        float s = -1e30f;
        if (j >= 0) {
            float acc = 0.f;
            const float4* kr = (const float4*)(buf + j * ATT_KS);
#pragma unroll
            for (int d4 = 0; d4 < 16; d4++) {
                float4 kv = kr[d4];
                acc += qr[4 * d4 + 0] * kv.x + qr[4 * d4 + 1] * kv.y
                     + qr[4 * d4 + 2] * kv.z + qr[4 * d4 + 3] * kv.w;
            }
            s = acc;
            m = fmaxf(m, s);
        }
        sc[tid * 65 + jj] = s;
    }

    float l = 0.f;
#pragma unroll
    for (int jj = 0; jj <= WIN; jj++) {
        int j = tid - WIN + jj;
        float p = 0.f;
        if (j >= 0) p = __expf(sc[tid * 65 + jj] - m);
        l += p;
        sc[tid * 65 + jj] = p;
    }
    __syncthreads();

    // ---- v tile (reuse buf) ----
    load_tile68(buf, v, base, tid);
    __syncthreads();

    // ---- P @ V over the band (vectorized) ----
    float acc[HD];
#pragma unroll
    for (int d = 0; d < HD; d++) acc[d] = 0.f;
#pragma unroll
    for (int jj = 0; jj <= WIN; jj++) {
        int j = tid - WIN + jj;
        if (j >= 0) {
            float p = sc[tid * 65 + jj];
            const float4* vr = (const float4*)(buf + j * ATT_KS);
#pragma unroll
            for (int d4 = 0; d4 < 16; d4++) {
                float4 vv = vr[d4];
                acc[4 * d4 + 0] += p * vv.x;
                acc[4 * d4 + 1] += p * vv.y;
                acc[4 * d4 + 2] += p * vv.z;
                acc[4 * d4 + 3] += p * vv.w;
            }
        }
    }
    const float rinv = 1.f / l;

    // ---- fused bf16 hi/lo split, direct 16B stores ----
    const size_t obase = base + (size_t)tid * D_MODEL;
#pragma unroll
    for (int g = 0; g < 8; g++) {
        __nv_bfloat16 hv[8], lv[8];
#pragma unroll
        for (int e = 0; e < 8; e++) {
            float o = acc[g * 8 + e] * rinv;
            hv[e] = __float2bfloat16(o);
            lv[e] = __float2bfloat16(o - __bfloat162float(hv[e]));
        }
        *(uint4*)(ohi + obase + g * 8) = *(uint4*)hv;
        *(uint4*)(olo + obase + g * 8) = *(uint4*)lv;
    }
}

// ---------------------------------------------------------------------------
extern "C" void kernel_launch(void* const* d_in, const int* in_sizes, int n_in,
                              void* d_out, int out_size)
{
    const float* x  = (const float*)d_in[0];
    const float* Wq = (const float*)d_in[1];
    const float* Wk = (const float*)d_in[2];
    const float* Wv = (const float*)d_in[3];
    const float* Wo = (const float*)d_in[4];
    float* out = (float*)d_out;

    float *q, *k, *v;
    __nv_bfloat16 *x_hi, *x_lo, *att_hi, *att_lo, *wt_hi, *wt_lo;
    cudaGetSymbolAddress((void**)&q, g_q);
    cudaGetSymbolAddress((void**)&k, g_k);
    cudaGetSymbolAddress((void**)&v, g_v);
    cudaGetSymbolAddress((void**)&x_hi, g_x_hi);
    cudaGetSymbolAddress((void**)&x_lo, g_x_lo);
    cudaGetSymbolAddress((void**)&att_hi, g_att_hi);
    cudaGetSymbolAddress((void**)&att_lo, g_att_lo);
    cudaGetSymbolAddress((void**)&wt_hi, g_wt_hi);
    cudaGetSymbolAddress((void**)&wt_lo, g_wt_lo);

    cudaFuncSetAttribute(gemm_mma_kernel,
                         cudaFuncAttributeMaxDynamicSharedMemorySize, GEMM_SMEM);
    cudaFuncSetAttribute(attn_kernel,
                         cudaFuncAttributeMaxDynamicSharedMemorySize, ATT_SMEM_BYTES);

    const size_t DD = (size_t)D_MODEL * D_MODEL;
    const int n4 = ROWS * D_MODEL / 4;

    // conversions
    split_kernel<<<(n4 + 255) / 256, 256>>>(x, x_hi, x_lo, n4);
    dim3 wgrid(32, 32), wblk(32, 8);
    wsplit_kernel<<<wgrid, wblk>>>(Wq, wt_hi + 0 * DD, wt_lo + 0 * DD);
    wsplit_kernel<<<wgrid, wblk>>>(Wk, wt_hi + 1 * DD, wt_lo + 1 * DD);
    wsplit_kernel<<<wgrid, wblk>>>(Wv, wt_hi + 2 * DD, wt_lo + 2 * DD);
    wsplit_kernel<<<wgrid, wblk>>>(Wo, wt_hi + 3 * DD, wt_lo + 3 * DD);

    // QKV projections on tensor cores (mma.sync)
    dim3 gg(D_MODEL / 128, ROWS / 128);   // (8, 256)
    gemm_mma_kernel<<<gg, 256, GEMM_SMEM>>>(x_hi, x_lo, wt_hi + 0 * DD, wt_lo + 0 * DD, q);
    gemm_mma_kernel<<<gg, 256, GEMM_SMEM>>>(x_hi, x_lo, wt_hi + 1 * DD, wt_lo + 1 * DD, k);
    gemm_mma_kernel<<<gg, 256, GEMM_SMEM>>>(x_hi, x_lo, wt_hi + 2 * DD, wt_lo + 2 * DD, v);

    // attention (writes bf16 hi/lo limbs directly)
    dim3 attn_grid(NH, NCHUNK, BATCH);
    attn_kernel<<<attn_grid, 256, ATT_SMEM_BYTES>>>(q, k, v, att_hi, att_lo);

    // output projection
    gemm_mma_kernel<<<gg, 256, GEMM_SMEM>>>(att_hi, att_lo, wt_hi + 3 * DD, wt_lo + 3 * DD, out);
}

// round 5
// speedup vs baseline: 3.1563x; 1.0701x over previous
#include <cuda_runtime.h>
#include <cuda_bf16.h>
#include <cstdint>

#define D_MODEL 1024
#define NH 16
#define HD 64
#define CHUNK 256
#define WIN 64
#define BATCH 4
#define SEQ 8192
#define NCHUNK (SEQ / CHUNK)
#define ROWS (BATCH * SEQ)

// ---------------- scratch (__device__ globals; no allocs allowed) ----------
__device__ float g_q[ROWS * D_MODEL];
__device__ float g_k[ROWS * D_MODEL];
__device__ float g_v[ROWS * D_MODEL];
__device__ __nv_bfloat16 g_x_hi[ROWS * D_MODEL];
__device__ __nv_bfloat16 g_x_lo[ROWS * D_MODEL];
__device__ __nv_bfloat16 g_att_hi[ROWS * D_MODEL];
__device__ __nv_bfloat16 g_att_lo[ROWS * D_MODEL];
// 4 transposed weights (q,k,v,o), hi/lo limbs, each [N=1024][K=1024] (K-major)
__device__ __nv_bfloat16 g_wt_hi[4 * D_MODEL * D_MODEL];
__device__ __nv_bfloat16 g_wt_lo[4 * D_MODEL * D_MODEL];

// ---------------------------------------------------------------------------
// helpers
// ---------------------------------------------------------------------------
__device__ __forceinline__ uint32_t smem_u32(const void* p) {
    uint32_t a;
    asm("{ .reg .u64 t; cvta.to.shared.u64 t, %1; cvt.u32.u64 %0, t; }"
        : "=r"(a) : "l"(p));
    return a;
}

__device__ __forceinline__ void cp_async16(uint32_t dst, const void* src) {
    asm volatile("cp.async.cg.shared.global [%0], [%1], 16;"
                 :: "r"(dst), "l"(src) : "memory");
}
__device__ __forceinline__ void cp_commit() {
    asm volatile("cp.async.commit_group;" ::: "memory");
}
__device__ __forceinline__ void cp_wait1() {
    asm volatile("cp.async.wait_group 1;" ::: "memory");
}

__device__ __forceinline__ void ldsm_x4(uint32_t* r, uint32_t addr) {
    asm volatile("ldmatrix.sync.aligned.m8n8.x4.shared.b16 {%0,%1,%2,%3}, [%4];"
                 : "=r"(r[0]), "=r"(r[1]), "=r"(r[2]), "=r"(r[3]) : "r"(addr));
}

__device__ __forceinline__ void mma16816(float* c, const uint32_t* a, const uint32_t* b) {
    asm volatile(
        "mma.sync.aligned.m16n8k16.row.col.f32.bf16.bf16.f32 "
        "{%0,%1,%2,%3}, {%4,%5,%6,%7}, {%8,%9}, {%0,%1,%2,%3};"
        : "+f"(c[0]), "+f"(c[1]), "+f"(c[2]), "+f"(c[3])
        : "r"(a[0]), "r"(a[1]), "r"(a[2]), "r"(a[3]), "r"(b[0]), "r"(b[1]));
}

// tile geometry: 128 rows x 32 bf16 cols = 64B rows, 4x 16B chunks per row
// swizzled 16B-chunk: c' = c ^ ((r>>1)&3)
#define TILE_B 8192
#define STAGE_B (4 * TILE_B)   // Ahi, Alo, Bhi, Blo
#define NSTAGE 3
#define GEMM_SMEM (NSTAGE * STAGE_B)  // 98304
#define KIT 32                 // 1024 / 32

__device__ __forceinline__ uint32_t sw_addr(uint32_t tile_base, int r, int c) {
    return tile_base + r * 64 + ((c ^ ((r >> 1) & 3)) << 4);
}

// ---------------------------------------------------------------------------
// Split fp32 -> bf16 hi/lo limbs
// ---------------------------------------------------------------------------
__global__ __launch_bounds__(256) void split_kernel(
    const float* __restrict__ in, __nv_bfloat16* __restrict__ hi,
    __nv_bfloat16* __restrict__ lo, int n4)
{
    int i = blockIdx.x * blockDim.x + threadIdx.x;
    if (i >= n4) return;
    float4 x = ((const float4*)in)[i];
    float v[4] = {x.x, x.y, x.z, x.w};
    __nv_bfloat16 h[4], l[4];
#pragma unroll
    for (int j = 0; j < 4; j++) {
        h[j] = __float2bfloat16(v[j]);
        l[j] = __float2bfloat16(v[j] - __bfloat162float(h[j]));
    }
    *(uint2*)(hi + 4 * (size_t)i) = *(uint2*)h;
    *(uint2*)(lo + 4 * (size_t)i) = *(uint2*)l;
}

// Weight transpose + split: hiT[n*1024+k] = split(W[k*1024+n])
__global__ __launch_bounds__(256) void wsplit_kernel(
    const float* __restrict__ W, __nv_bfloat16* __restrict__ hiT,
    __nv_bfloat16* __restrict__ loT)
{
    __shared__ float tile[32][33];
    int bx = blockIdx.x * 32, by = blockIdx.y * 32;
    int tx = threadIdx.x, ty = threadIdx.y;  // 32x8
#pragma unroll
    for (int r = ty; r < 32; r += 8)
        tile[r][tx] = W[(size_t)(by + r) * D_MODEL + bx + tx];
    __syncthreads();
#pragma unroll
    for (int r = ty; r < 32; r += 8) {
        float v = tile[tx][r];  // = W[(by+tx)*D + bx+r]
        __nv_bfloat16 h = __float2bfloat16(v);
        size_t o = (size_t)(bx + r) * D_MODEL + by + tx;
        hiT[o] = h;
        loT[o] = __float2bfloat16(v - __bfloat162float(h));
    }
}

// ---------------------------------------------------------------------------
// bf16-split GEMM via mma.sync: C[M,1024] = (Ahi+Alo) @ (Bhi+Blo)^T, fp32 acc
// CTA 128x128, BK=32, 3-stage cp.async pipeline, 8 warps (2m x 4n),
// 2 CTAs/SM. Single barrier per mainloop iteration.
// ---------------------------------------------------------------------------
__global__ __launch_bounds__(256, 2) void gemm_mma_kernel(
    const __nv_bfloat16* __restrict__ Ahi, const __nv_bfloat16* __restrict__ Alo,
    const __nv_bfloat16* __restrict__ Bhi, const __nv_bfloat16* __restrict__ Blo,
    float* __restrict__ C)
{
    extern __shared__ char smem[];
    const uint32_t sbase = smem_u32(smem);
    const int tid = threadIdx.x;
    const int lane = tid & 31;
    const int wid = tid >> 5;
    const int wm = wid >> 2;        // 0..1
    const int wn = wid & 3;         // 0..3
    const int m0 = blockIdx.y * 128;
    const int n0 = blockIdx.x * 128;

    const __nv_bfloat16* srcs[4] = {Ahi, Alo, Bhi, Blo};

    auto load_stage = [&](int stage, int k0) {
        uint32_t sb = sbase + stage * STAGE_B;
#pragma unroll
        for (int t = 0; t < 4; t++) {
            int row0 = (t < 2) ? m0 : n0;
            const __nv_bfloat16* s = srcs[t];
#pragma unroll
            for (int i = 0; i < 2; i++) {
                int cid = tid + i * 256;       // 0..511
                int r = cid >> 2;
                int c = cid & 3;
                const void* g = s + (size_t)(row0 + r) * D_MODEL + k0 + c * 8;
                cp_async16(sw_addr(sb + t * TILE_B, r, c), g);
            }
        }
    };

    float acc[4][4][4];
#pragma unroll
    for (int i = 0; i < 4; i++)
#pragma unroll
        for (int j = 0; j < 4; j++)
#pragma unroll
            for (int e = 0; e < 4; e++) acc[i][j][e] = 0.f;

    load_stage(0, 0);
    cp_commit();
    load_stage(1, 32);
    cp_commit();

    const int a_r = lane & 15;
    const int a_c = lane >> 4;
    const int b_r = (lane & 7) + ((lane >> 4) << 3);
    const int b_c = (lane >> 3) & 1;

    for (int it = 0; it < KIT; it++) {
        cp_wait1();
        __syncthreads();           // stage `it` visible; all readers past stage it%3
        if (it + 2 < KIT) load_stage((it + 2) % NSTAGE, (it + 2) * 32);
        cp_commit();

        const uint32_t sb = sbase + (it % NSTAGE) * STAGE_B;
        const uint32_t tAhi = sb;
        const uint32_t tAlo = sb + TILE_B;
        const uint32_t tBhi = sb + 2 * TILE_B;
        const uint32_t tBlo = sb + 3 * TILE_B;

#pragma unroll
        for (int ks = 0; ks < 2; ks++) {
            uint32_t a[4][4], bh[4][2], bl[4][2];
            // load ALL B fragments + A_hi up front (hide LDSM latency)
#pragma unroll
            for (int mt = 0; mt < 4; mt++) {
                int r = wm * 64 + mt * 16 + a_r;
                ldsm_x4(a[mt], sw_addr(tAhi, r, ks * 2 + a_c));
            }
#pragma unroll
            for (int np = 0; np < 2; np++) {
                uint32_t t4[4];
                int r = wn * 32 + np * 16 + b_r;
                ldsm_x4(t4, sw_addr(tBhi, r, ks * 2 + b_c));
                bh[np * 2][0] = t4[0]; bh[np * 2][1] = t4[1];
                bh[np * 2 + 1][0] = t4[2]; bh[np * 2 + 1][1] = t4[3];
            }
#pragma unroll
            for (int np = 0; np < 2; np++) {
                uint32_t t4[4];
                int r = wn * 32 + np * 16 + b_r;
                ldsm_x4(t4, sw_addr(tBlo, r, ks * 2 + b_c));
                bl[np * 2][0] = t4[0]; bl[np * 2][1] = t4[1];
                bl[np * 2 + 1][0] = t4[2]; bl[np * 2 + 1][1] = t4[3];
            }
            // pass 1: hi*hi
#pragma unroll
            for (int mt = 0; mt < 4; mt++)
#pragma unroll
                for (int nt = 0; nt < 4; nt++)
                    mma16816(acc[mt][nt], a[mt], bh[nt]);
            // pass 2: hi*lo
#pragma unroll
            for (int mt = 0; mt < 4; mt++)
#pragma unroll
                for (int nt = 0; nt < 4; nt++)
                    mma16816(acc[mt][nt], a[mt], bl[nt]);
            // A_lo (reuse a regs)
#pragma unroll
            for (int mt = 0; mt < 4; mt++) {
                int r = wm * 64 + mt * 16 + a_r;
                ldsm_x4(a[mt], sw_addr(tAlo, r, ks * 2 + a_c));
            }
            // pass 3: lo*hi
#pragma unroll
            for (int mt = 0; mt < 4; mt++)
#pragma unroll
                for (int nt = 0; nt < 4; nt++)
                    mma16816(acc[mt][nt], a[mt], bh[nt]);
        }
        // no trailing sync: next iteration's wait+sync orders stage reuse
    }

    const int er = lane >> 2;
    const int ec = (lane & 3) * 2;
#pragma unroll
    for (int mt = 0; mt < 4; mt++) {
#pragma unroll
        for (int nt = 0; nt < 4; nt++) {
            int row = m0 + wm * 64 + mt * 16 + er;
            int col = n0 + wn * 32 + nt * 8 + ec;
            *(float2*)(C + (size_t)row * D_MODEL + col) =
                make_float2(acc[mt][nt][0], acc[mt][nt][1]);
            *(float2*)(C + (size_t)(row + 8) * D_MODEL + col) =
                make_float2(acc[mt][nt][2], acc[mt][nt][3]);
        }
    }
}

// ---------------------------------------------------------------------------
// Banded chunk-local attention: 128 threads/CTA, 2 adjacent queries/thread
// (shares k/v row loads between queries 2t and 2t+1 -> half the LDS traffic).
// k/v smem layout: row stride 64 floats (256B), 16B chunks XOR-swizzled by
// ((r>>1)&7) so 8 consecutive even (or odd) rows hit distinct banks.
// Fused bf16 hi/lo output split.
// ---------------------------------------------------------------------------
#define ATT_SC 66
#define ATT_SMEM_BYTES ((CHUNK * 64 + CHUNK * ATT_SC) * 4)  // 133120

__device__ __forceinline__ int att_addr(int r, int c) {  // float index
    return r * 64 + ((c ^ ((r >> 1) & 7)) << 2);
}

__device__ __forceinline__ void att_load_tile(
    float* __restrict__ buf, const float* __restrict__ src, size_t base, int tid)
{
#pragma unroll
    for (int i = 0; i < 32; i++) {
        int idx = tid + i * 128;          // 0..4095
        int r = idx >> 4;
        int c = idx & 15;
        float4 t = *(const float4*)(src + base + (size_t)r * D_MODEL + c * 4);
        *(float4*)(buf + att_addr(r, c)) = t;
    }
}

__global__ __launch_bounds__(128) void attn_kernel(
    const float* __restrict__ q, const float* __restrict__ k,
    const float* __restrict__ v,
    __nv_bfloat16* __restrict__ ohi, __nv_bfloat16* __restrict__ olo)
{
    extern __shared__ float fsmem[];
    float* buf = fsmem;                      // [256][64] swizzled
    float* sc  = fsmem + CHUNK * 64;         // [256][66]

    const int h = blockIdx.x;
    const int n = blockIdx.y;
    const int b = blockIdx.z;
    const int t = threadIdx.x;               // 0..127
    const int q0 = 2 * t;
    const int q1 = 2 * t + 1;

    const size_t base = ((size_t)(b * SEQ + n * CHUNK)) * D_MODEL + h * HD;

    // ---- stage q, pull both rows into registers (pre-scaled) ----
    att_load_tile(buf, q, base, t);
    __syncthreads();
    float qr0[HD], qr1[HD];
#pragma unroll
    for (int c = 0; c < 16; c++) {
        float4 t0 = *(const float4*)(buf + att_addr(q0, c));
        float4 t1 = *(const float4*)(buf + att_addr(q1, c));
        qr0[4 * c + 0] = t0.x * 0.125f; qr0[4 * c + 1] = t0.y * 0.125f;
        qr0[4 * c + 2] = t0.z * 0.125f; qr0[4 * c + 3] = t0.w * 0.125f;
        qr1[4 * c + 0] = t1.x * 0.125f; qr1[4 * c + 1] = t1.y * 0.125f;
        qr1[4 * c + 2] = t1.z * 0.125f; qr1[4 * c + 3] = t1.w * 0.125f;
    }
    __syncthreads();

    // ---- k tile ----
    att_load_tile(buf, k, base, t);
    __syncthreads();

    // ---- scores over the band; one k-row load serves both queries ----
    float m0 = -1e30f, m1 = -1e30f;
#pragma unroll 2
    for (int ju = 0; ju <= 65; ju++) {
        int j = q0 - 64 + ju;                 // key row
        float s0 = -1e30f, s1 = -1e30f;
        if (j >= 0) {
            float a0 = 0.f, a1 = 0.f;
#pragma unroll
            for (int c = 0; c < 16; c++) {
                float4 kv = *(const float4*)(buf + att_addr(j, c));
                a0 += qr0[4 * c + 0] * kv.x + qr0[4 * c + 1] * kv.y
                    + qr0[4 * c + 2] * kv.z + qr0[4 * c + 3] * kv.w;
                a1 += qr1[4 * c + 0] * kv.x + qr1[4 * c + 1] * kv.y
                    + qr1[4 * c + 2] * kv.z + qr1[4 * c + 3] * kv.w;
            }
            if (ju <= 64) { s0 = a0; m0 = fmaxf(m0, s0); }
            if (ju >= 1)  { s1 = a1; m1 = fmaxf(m1, s1); }
        }
        sc[q0 * ATT_SC + ju] = s0;
        sc[q1 * ATT_SC + ju] = s1;
    }

    // ---- softmax (sentinel -1e30 -> exp underflows to 0, masks invalid) ----
    float l0 = 0.f, l1 = 0.f;
#pragma unroll 2
    for (int ju = 0; ju <= 65; ju++) {
        float p0 = __expf(sc[q0 * ATT_SC + ju] - m0);
        float p1 = __expf(sc[q1 * ATT_SC + ju] - m1);
        l0 += p0; l1 += p1;
        sc[q0 * ATT_SC + ju] = p0;
        sc[q1 * ATT_SC + ju] = p1;
    }
    __syncthreads();

    // ---- v tile (reuse buf) ----
    att_load_tile(buf, v, base, t);
    __syncthreads();

    // ---- P @ V; one v-row load serves both queries ----
    float a0[HD], a1[HD];
#pragma unroll
    for (int d = 0; d < HD; d++) { a0[d] = 0.f; a1[d] = 0.f; }
#pragma unroll 2
    for (int ju = 0; ju <= 65; ju++) {
        int j = q0 - 64 + ju;
        if (j >= 0) {
            float p0 = sc[q0 * ATT_SC + ju];
            float p1 = sc[q1 * ATT_SC + ju];
#pragma unroll
            for (int c = 0; c < 16; c++) {
                float4 vv = *(const float4*)(buf + att_addr(j, c));
                a0[4 * c + 0] += p0 * vv.x; a0[4 * c + 1] += p0 * vv.y;
                a0[4 * c + 2] += p0 * vv.z; a0[4 * c + 3] += p0 * vv.w;
                a1[4 * c + 0] += p1 * vv.x; a1[4 * c + 1] += p1 * vv.y;
                a1[4 * c + 2] += p1 * vv.z; a1[4 * c + 3] += p1 * vv.w;
            }
        }
    }
    const float r0 = 1.f / l0;
    const float r1 = 1.f / l1;

    // ---- fused bf16 hi/lo split, direct 16B stores (2 rows) ----
#pragma unroll
    for (int g = 0; g < 8; g++) {
        __nv_bfloat16 hv0[8], lv0[8], hv1[8], lv1[8];
#pragma unroll
        for (int e = 0; e < 8; e++) {
            float o0 = a0[g * 8 + e] * r0;
            hv0[e] = __float2bfloat16(o0);
            lv0[e] = __float2bfloat16(o0 - __bfloat162float(hv0[e]));
            float o1 = a1[g * 8 + e] * r1;
            hv1[e] = __float2bfloat16(o1);
            lv1[e] = __float2bfloat16(o1 - __bfloat162float(hv1[e]));
        }
        *(uint4*)(ohi + base + (size_t)q0 * D_MODEL + g * 8) = *(uint4*)hv0;
        *(uint4*)(olo + base + (size_t)q0 * D_MODEL + g * 8) = *(uint4*)lv0;
        *(uint4*)(ohi + base + (size_t)q1 * D_MODEL + g * 8) = *(uint4*)hv1;
        *(uint4*)(olo + base + (size_t)q1 * D_MODEL + g * 8) = *(uint4*)lv1;
    }
}

// ---------------------------------------------------------------------------
extern "C" void kernel_launch(void* const* d_in, const int* in_sizes, int n_in,
                              void* d_out, int out_size)
{
    const float* x  = (const float*)d_in[0];
    const float* Wq = (const float*)d_in[1];
    const float* Wk = (const float*)d_in[2];
    const float* Wv = (const float*)d_in[3];
    const float* Wo = (const float*)d_in[4];
    float* out = (float*)d_out;

    float *q, *k, *v;
    __nv_bfloat16 *x_hi, *x_lo, *att_hi, *att_lo, *wt_hi, *wt_lo;
    cudaGetSymbolAddress((void**)&q, g_q);
    cudaGetSymbolAddress((void**)&k, g_k);
    cudaGetSymbolAddress((void**)&v, g_v);
    cudaGetSymbolAddress((void**)&x_hi, g_x_hi);
    cudaGetSymbolAddress((void**)&x_lo, g_x_lo);
    cudaGetSymbolAddress((void**)&att_hi, g_att_hi);
    cudaGetSymbolAddress((void**)&att_lo, g_att_lo);
    cudaGetSymbolAddress((void**)&wt_hi, g_wt_hi);
    cudaGetSymbolAddress((void**)&wt_lo, g_wt_lo);

    cudaFuncSetAttribute(gemm_mma_kernel,
                         cudaFuncAttributeMaxDynamicSharedMemorySize, GEMM_SMEM);
    cudaFuncSetAttribute(attn_kernel,
                         cudaFuncAttributeMaxDynamicSharedMemorySize, ATT_SMEM_BYTES);

    const size_t DD = (size_t)D_MODEL * D_MODEL;
    const int n4 = ROWS * D_MODEL / 4;
    dim3 wgrid(32, 32), wblk(32, 8);
    dim3 gg(D_MODEL / 128, ROWS / 128);   // (8, 256)

    // launches 1-4: input split + QKV weight splits
    split_kernel<<<(n4 + 255) / 256, 256>>>(x, x_hi, x_lo, n4);
    wsplit_kernel<<<wgrid, wblk>>>(Wq, wt_hi + 0 * DD, wt_lo + 0 * DD);
    wsplit_kernel<<<wgrid, wblk>>>(Wk, wt_hi + 1 * DD, wt_lo + 1 * DD);
    wsplit_kernel<<<wgrid, wblk>>>(Wv, wt_hi + 2 * DD, wt_lo + 2 * DD);

    // launch 5: gemm Q  (placed here so ncu -s 5 -c 1 captures a GEMM)
    gemm_mma_kernel<<<gg, 256, GEMM_SMEM>>>(x_hi, x_lo, wt_hi + 0 * DD, wt_lo + 0 * DD, q);

    wsplit_kernel<<<wgrid, wblk>>>(Wo, wt_hi + 3 * DD, wt_lo + 3 * DD);
    gemm_mma_kernel<<<gg, 256, GEMM_SMEM>>>(x_hi, x_lo, wt_hi + 1 * DD, wt_lo + 1 * DD, k);
    gemm_mma_kernel<<<gg, 256, GEMM_SMEM>>>(x_hi, x_lo, wt_hi + 2 * DD, wt_lo + 2 * DD, v);

    // attention (128 threads, 2 queries/thread; writes bf16 limbs directly)
    dim3 attn_grid(NH, NCHUNK, BATCH);
    attn_kernel<<<attn_grid, 128, ATT_SMEM_BYTES>>>(q, k, v, att_hi, att_lo);

    // output projection
    gemm_mma_kernel<<<gg, 256, GEMM_SMEM>>>(att_hi, att_lo, wt_hi + 3 * DD, wt_lo + 3 * DD, out);
}

// round 6
// speedup vs baseline: 3.2031x; 1.0148x over previous
#include <cuda_runtime.h>
#include <cuda_bf16.h>
#include <cstdint>

#define D_MODEL 1024
#define NH 16
#define HD 64
#define CHUNK 256
#define WIN 64
#define BATCH 4
#define SEQ 8192
#define NCHUNK (SEQ / CHUNK)
#define ROWS (BATCH * SEQ)

// ---------------- scratch (__device__ globals; no allocs allowed) ----------
__device__ float g_q[ROWS * D_MODEL];
__device__ float g_k[ROWS * D_MODEL];
__device__ float g_v[ROWS * D_MODEL];
__device__ __nv_bfloat16 g_x_hi[ROWS * D_MODEL];
__device__ __nv_bfloat16 g_x_lo[ROWS * D_MODEL];
__device__ __nv_bfloat16 g_att_hi[ROWS * D_MODEL];
__device__ __nv_bfloat16 g_att_lo[ROWS * D_MODEL];
// 4 transposed weights (q,k,v,o), hi/lo limbs, each [N=1024][K=1024] (K-major)
__device__ __nv_bfloat16 g_wt_hi[4 * D_MODEL * D_MODEL];
__device__ __nv_bfloat16 g_wt_lo[4 * D_MODEL * D_MODEL];

// ---------------------------------------------------------------------------
// helpers
// ---------------------------------------------------------------------------
__device__ __forceinline__ uint32_t smem_u32(const void* p) {
    uint32_t a;
    asm("{ .reg .u64 t; cvta.to.shared.u64 t, %1; cvt.u32.u64 %0, t; }"
        : "=r"(a) : "l"(p));
    return a;
}

__device__ __forceinline__ void cp_async16(uint32_t dst, const void* src) {
    asm volatile("cp.async.cg.shared.global [%0], [%1], 16;"
                 :: "r"(dst), "l"(src) : "memory");
}
__device__ __forceinline__ void cp_commit() {
    asm volatile("cp.async.commit_group;" ::: "memory");
}
__device__ __forceinline__ void cp_wait1() {
    asm volatile("cp.async.wait_group 1;" ::: "memory");
}

__device__ __forceinline__ void ldsm_x4(uint32_t* r, uint32_t addr) {
    asm volatile("ldmatrix.sync.aligned.m8n8.x4.shared.b16 {%0,%1,%2,%3}, [%4];"
                 : "=r"(r[0]), "=r"(r[1]), "=r"(r[2]), "=r"(r[3]) : "r"(addr));
}

__device__ __forceinline__ void mma16816(float* c, const uint32_t* a, const uint32_t* b) {
    asm volatile(
        "mma.sync.aligned.m16n8k16.row.col.f32.bf16.bf16.f32 "
        "{%0,%1,%2,%3}, {%4,%5,%6,%7}, {%8,%9}, {%0,%1,%2,%3};"
        : "+f"(c[0]), "+f"(c[1]), "+f"(c[2]), "+f"(c[3])
        : "r"(a[0]), "r"(a[1]), "r"(a[2]), "r"(a[3]), "r"(b[0]), "r"(b[1]));
}

// ---- packed f32x2 ops (FFMA2 path, PTX-only per SASS_QUICKREF) ----
__device__ __forceinline__ uint64_t pack2f(float lo, float hi) {
    uint64_t r;
    asm("mov.b64 %0, {%1,%2};" : "=l"(r) : "f"(lo), "f"(hi));
    return r;
}
__device__ __forceinline__ void unpack2f(uint64_t p, float& lo, float& hi) {
    asm("mov.b64 {%0,%1}, %2;" : "=f"(lo), "=f"(hi) : "l"(p));
}
__device__ __forceinline__ void fma2(uint64_t& d, uint64_t a, uint64_t b) {
    asm("fma.rn.f32x2 %0, %1, %2, %0;" : "+l"(d) : "l"(a), "l"(b));
}
__device__ __forceinline__ uint64_t mul2(uint64_t a, uint64_t b) {
    uint64_t r;
    asm("mul.rn.f32x2 %0, %1, %2;" : "=l"(r) : "l"(a), "l"(b));
    return r;
}
__device__ __forceinline__ void lds_v2u64(uint64_t& a, uint64_t& b, uint32_t addr) {
    asm volatile("ld.shared.v2.b64 {%0,%1}, [%2];" : "=l"(a), "=l"(b) : "r"(addr));
}

// tile geometry: 128 rows x 32 bf16 cols = 64B rows, 4x 16B chunks per row
// swizzled 16B-chunk: c' = c ^ ((r>>1)&3)
#define TILE_B 8192
#define STAGE_B (4 * TILE_B)   // Ahi, Alo, Bhi, Blo
#define NSTAGE 3
#define GEMM_SMEM (NSTAGE * STAGE_B)  // 98304
#define KIT 32                 // 1024 / 32

__device__ __forceinline__ uint32_t sw_addr(uint32_t tile_base, int r, int c) {
    return tile_base + r * 64 + ((c ^ ((r >> 1) & 3)) << 4);
}

// ---------------------------------------------------------------------------
// Split fp32 -> bf16 hi/lo limbs
// ---------------------------------------------------------------------------
__global__ __launch_bounds__(256) void split_kernel(
    const float* __restrict__ in, __nv_bfloat16* __restrict__ hi,
    __nv_bfloat16* __restrict__ lo, int n4)
{
    int i = blockIdx.x * blockDim.x + threadIdx.x;
    if (i >= n4) return;
    float4 x = ((const float4*)in)[i];
    float v[4] = {x.x, x.y, x.z, x.w};
    __nv_bfloat16 h[4], l[4];
#pragma unroll
    for (int j = 0; j < 4; j++) {
        h[j] = __float2bfloat16(v[j]);
        l[j] = __float2bfloat16(v[j] - __bfloat162float(h[j]));
    }
    *(uint2*)(hi + 4 * (size_t)i) = *(uint2*)h;
    *(uint2*)(lo + 4 * (size_t)i) = *(uint2*)l;
}

// Weight transpose + split: hiT[n*1024+k] = split(W[k*1024+n])
__global__ __launch_bounds__(256) void wsplit_kernel(
    const float* __restrict__ W, __nv_bfloat16* __restrict__ hiT,
    __nv_bfloat16* __restrict__ loT)
{
    __shared__ float tile[32][33];
    int bx = blockIdx.x * 32, by = blockIdx.y * 32;
    int tx = threadIdx.x, ty = threadIdx.y;  // 32x8
#pragma unroll
    for (int r = ty; r < 32; r += 8)
        tile[r][tx] = W[(size_t)(by + r) * D_MODEL + bx + tx];
    __syncthreads();
#pragma unroll
    for (int r = ty; r < 32; r += 8) {
        float v = tile[tx][r];  // = W[(by+tx)*D + bx+r]
        __nv_bfloat16 h = __float2bfloat16(v);
        size_t o = (size_t)(bx + r) * D_MODEL + by + tx;
        hiT[o] = h;
        loT[o] = __float2bfloat16(v - __bfloat162float(h));
    }
}

// ---------------------------------------------------------------------------
// bf16-split GEMM via mma.sync: C[M,1024] = (Ahi+Alo) @ (Bhi+Blo)^T, fp32 acc
// CTA 128x128, BK=32, 3-stage cp.async pipeline, 8 warps (2m x 4n),
// 2 CTAs/SM. Single barrier per mainloop iteration.
// ---------------------------------------------------------------------------
__global__ __launch_bounds__(256, 2) void gemm_mma_kernel(
    const __nv_bfloat16* __restrict__ Ahi, const __nv_bfloat16* __restrict__ Alo,
    const __nv_bfloat16* __restrict__ Bhi, const __nv_bfloat16* __restrict__ Blo,
    float* __restrict__ C)
{
    extern __shared__ char smem[];
    const uint32_t sbase = smem_u32(smem);
    const int tid = threadIdx.x;
    const int lane = tid & 31;
    const int wid = tid >> 5;
    const int wm = wid >> 2;        // 0..1
    const int wn = wid & 3;         // 0..3
    const int m0 = blockIdx.y * 128;
    const int n0 = blockIdx.x * 128;

    const __nv_bfloat16* srcs[4] = {Ahi, Alo, Bhi, Blo};

    auto load_stage = [&](int stage, int k0) {
        uint32_t sb = sbase + stage * STAGE_B;
#pragma unroll
        for (int t = 0; t < 4; t++) {
            int row0 = (t < 2) ? m0 : n0;
            const __nv_bfloat16* s = srcs[t];
#pragma unroll
            for (int i = 0; i < 2; i++) {
                int cid = tid + i * 256;       // 0..511
                int r = cid >> 2;
                int c = cid & 3;
                const void* g = s + (size_t)(row0 + r) * D_MODEL + k0 + c * 8;
                cp_async16(sw_addr(sb + t * TILE_B, r, c), g);
            }
        }
    };

    float acc[4][4][4];
#pragma unroll
    for (int i = 0; i < 4; i++)
#pragma unroll
        for (int j = 0; j < 4; j++)
#pragma unroll
            for (int e = 0; e < 4; e++) acc[i][j][e] = 0.f;

    load_stage(0, 0);
    cp_commit();
    load_stage(1, 32);
    cp_commit();

    const int a_r = lane & 15;
    const int a_c = lane >> 4;
    const int b_r = (lane & 7) + ((lane >> 4) << 3);
    const int b_c = (lane >> 3) & 1;

    for (int it = 0; it < KIT; it++) {
        cp_wait1();
        __syncthreads();
        if (it + 2 < KIT) load_stage((it + 2) % NSTAGE, (it + 2) * 32);
        cp_commit();

        const uint32_t sb = sbase + (it % NSTAGE) * STAGE_B;
        const uint32_t tAhi = sb;
        const uint32_t tAlo = sb + TILE_B;
        const uint32_t tBhi = sb + 2 * TILE_B;
        const uint32_t tBlo = sb + 3 * TILE_B;

#pragma unroll
        for (int ks = 0; ks < 2; ks++) {
            uint32_t a[4][4], bh[4][2], bl[4][2];
#pragma unroll
            for (int mt = 0; mt < 4; mt++) {
                int r = wm * 64 + mt * 16 + a_r;
                ldsm_x4(a[mt], sw_addr(tAhi, r, ks * 2 + a_c));
            }
#pragma unroll
            for (int np = 0; np < 2; np++) {
                uint32_t t4[4];
                int r = wn * 32 + np * 16 + b_r;
                ldsm_x4(t4, sw_addr(tBhi, r, ks * 2 + b_c));
                bh[np * 2][0] = t4[0]; bh[np * 2][1] = t4[1];
                bh[np * 2 + 1][0] = t4[2]; bh[np * 2 + 1][1] = t4[3];
            }
#pragma unroll
            for (int np = 0; np < 2; np++) {
                uint32_t t4[4];
                int r = wn * 32 + np * 16 + b_r;
                ldsm_x4(t4, sw_addr(tBlo, r, ks * 2 + b_c));
                bl[np * 2][0] = t4[0]; bl[np * 2][1] = t4[1];
                bl[np * 2 + 1][0] = t4[2]; bl[np * 2 + 1][1] = t4[3];
            }
#pragma unroll
            for (int mt = 0; mt < 4; mt++)
#pragma unroll
                for (int nt = 0; nt < 4; nt++)
                    mma16816(acc[mt][nt], a[mt], bh[nt]);
#pragma unroll
            for (int mt = 0; mt < 4; mt++)
#pragma unroll
                for (int nt = 0; nt < 4; nt++)
                    mma16816(acc[mt][nt], a[mt], bl[nt]);
#pragma unroll
            for (int mt = 0; mt < 4; mt++) {
                int r = wm * 64 + mt * 16 + a_r;
                ldsm_x4(a[mt], sw_addr(tAlo, r, ks * 2 + a_c));
            }
#pragma unroll
            for (int mt = 0; mt < 4; mt++)
#pragma unroll
                for (int nt = 0; nt < 4; nt++)
                    mma16816(acc[mt][nt], a[mt], bh[nt]);
        }
    }

    const int er = lane >> 2;
    const int ec = (lane & 3) * 2;
#pragma unroll
    for (int mt = 0; mt < 4; mt++) {
#pragma unroll
        for (int nt = 0; nt < 4; nt++) {
            int row = m0 + wm * 64 + mt * 16 + er;
            int col = n0 + wn * 32 + nt * 8 + ec;
            *(float2*)(C + (size_t)row * D_MODEL + col) =
                make_float2(acc[mt][nt][0], acc[mt][nt][1]);
            *(float2*)(C + (size_t)(row + 8) * D_MODEL + col) =
                make_float2(acc[mt][nt][2], acc[mt][nt][3]);
        }
    }
}

// ---------------------------------------------------------------------------
// Banded chunk-local attention: 128 threads/CTA, 2 adjacent queries/thread,
// packed-f32x2 (FFMA2) math on the dim axis. k/v smem rows stride 64 floats,
// 16B chunks XOR-swizzled by ((r>>1)&7). Fused bf16 hi/lo output split.
// ---------------------------------------------------------------------------
#define ATT_SC 66
#define ATT_SMEM_BYTES ((CHUNK * 64 + CHUNK * ATT_SC) * 4)  // 133120

__device__ __forceinline__ int att_addr(int r, int c) {  // float index, c = 16B chunk
    return r * 64 + ((c ^ ((r >> 1) & 7)) << 2);
}

__device__ __forceinline__ void att_load_tile(
    float* __restrict__ buf, const float* __restrict__ src, size_t base, int tid)
{
#pragma unroll
    for (int i = 0; i < 32; i++) {
        int idx = tid + i * 128;          // 0..4095
        int r = idx >> 4;
        int c = idx & 15;
        float4 t = *(const float4*)(src + base + (size_t)r * D_MODEL + c * 4);
        *(float4*)(buf + att_addr(r, c)) = t;
    }
}

__global__ __launch_bounds__(128) void attn_kernel(
    const float* __restrict__ q, const float* __restrict__ k,
    const float* __restrict__ v,
    __nv_bfloat16* __restrict__ ohi, __nv_bfloat16* __restrict__ olo)
{
    extern __shared__ float fsmem[];
    float* buf = fsmem;                      // [256][64] swizzled
    float* sc  = fsmem + CHUNK * 64;         // [256][66]
    const uint32_t sb = smem_u32(fsmem);

    const int h = blockIdx.x;
    const int n = blockIdx.y;
    const int b = blockIdx.z;
    const int t = threadIdx.x;               // 0..127
    const int q0 = 2 * t;
    const int q1 = 2 * t + 1;

    const size_t base = ((size_t)(b * SEQ + n * CHUNK)) * D_MODEL + h * HD;

    // ---- stage q, pull both rows into packed registers (pre-scaled) ----
    att_load_tile(buf, q, base, t);
    __syncthreads();
    uint64_t qp0[32], qp1[32];
    {
        const uint64_t scale2 = pack2f(0.125f, 0.125f);
#pragma unroll
        for (int c = 0; c < 16; c++) {
            uint64_t a, bq;
            lds_v2u64(a, bq, sb + 4 * att_addr(q0, c));
            qp0[2 * c] = mul2(a, scale2); qp0[2 * c + 1] = mul2(bq, scale2);
            lds_v2u64(a, bq, sb + 4 * att_addr(q1, c));
            qp1[2 * c] = mul2(a, scale2); qp1[2 * c + 1] = mul2(bq, scale2);
        }
    }
    __syncthreads();

    // ---- k tile ----
    att_load_tile(buf, k, base, t);
    __syncthreads();

    // ---- scores over the band; one k-row load serves both queries ----
    const uint64_t zero2 = pack2f(0.f, 0.f);
    float m0 = -1e30f, m1 = -1e30f;
#pragma unroll 2
    for (int ju = 0; ju <= 65; ju++) {
        int j = q0 - 64 + ju;                 // key row
        float s0 = -1e30f, s1 = -1e30f;
        if (j >= 0) {
            uint64_t acc0 = zero2, acc1 = zero2;
#pragma unroll
            for (int c = 0; c < 16; c += 2) {   // 2 chunks = 8 floats per step
                uint64_t k0, k1, k2, k3;
                lds_v2u64(k0, k1, sb + 4 * att_addr(j, c));
                lds_v2u64(k2, k3, sb + 4 * att_addr(j, c + 1));
                fma2(acc0, qp0[2 * c], k0);     fma2(acc1, qp1[2 * c], k0);
                fma2(acc0, qp0[2 * c + 1], k1); fma2(acc1, qp1[2 * c + 1], k1);
                fma2(acc0, qp0[2 * c + 2], k2); fma2(acc1, qp1[2 * c + 2], k2);
                fma2(acc0, qp0[2 * c + 3], k3); fma2(acc1, qp1[2 * c + 3], k3);
            }
            float e0, o0, e1, o1;
            unpack2f(acc0, e0, o0);
            unpack2f(acc1, e1, o1);
            if (ju <= 64) { s0 = e0 + o0; m0 = fmaxf(m0, s0); }
            if (ju >= 1)  { s1 = e1 + o1; m1 = fmaxf(m1, s1); }
        }
        sc[q0 * ATT_SC + ju] = s0;
        sc[q1 * ATT_SC + ju] = s1;
    }

    // ---- softmax (sentinel -1e30 -> exp underflows to 0) ----
    float l0 = 0.f, l1 = 0.f;
#pragma unroll 2
    for (int ju = 0; ju <= 65; ju++) {
        float p0 = __expf(sc[q0 * ATT_SC + ju] - m0);
        float p1 = __expf(sc[q1 * ATT_SC + ju] - m1);
        l0 += p0; l1 += p1;
        sc[q0 * ATT_SC + ju] = p0;
        sc[q1 * ATT_SC + ju] = p1;
    }
    __syncthreads();

    // ---- v tile (reuse buf) ----
    att_load_tile(buf, v, base, t);
    __syncthreads();

    // ---- P @ V; packed accumulators over dim pairs ----
    uint64_t ap0[32], ap1[32];
#pragma unroll
    for (int i = 0; i < 32; i++) { ap0[i] = zero2; ap1[i] = zero2; }
#pragma unroll 2
    for (int ju = 0; ju <= 65; ju++) {
        int j = q0 - 64 + ju;
        if (j >= 0) {
            float p0 = sc[q0 * ATT_SC + ju];
            float p1 = sc[q1 * ATT_SC + ju];
            uint64_t pp0 = pack2f(p0, p0);
            uint64_t pp1 = pack2f(p1, p1);
#pragma unroll
            for (int c = 0; c < 16; c += 2) {
                uint64_t v0, v1, v2, v3;
                lds_v2u64(v0, v1, sb + 4 * att_addr(j, c));
                lds_v2u64(v2, v3, sb + 4 * att_addr(j, c + 1));
                fma2(ap0[2 * c], pp0, v0);     fma2(ap1[2 * c], pp1, v0);
                fma2(ap0[2 * c + 1], pp0, v1); fma2(ap1[2 * c + 1], pp1, v1);
                fma2(ap0[2 * c + 2], pp0, v2); fma2(ap1[2 * c + 2], pp1, v2);
                fma2(ap0[2 * c + 3], pp0, v3); fma2(ap1[2 * c + 3], pp1, v3);
            }
        }
    }
    const float r0 = 1.f / l0;
    const float r1 = 1.f / l1;

    // ---- fused bf16 hi/lo split, direct 16B stores (2 rows) ----
#pragma unroll
    for (int g = 0; g < 8; g++) {          // 8 dims per group = 4 packed pairs
        __nv_bfloat16 hv0[8], lv0[8], hv1[8], lv1[8];
#pragma unroll
        for (int e = 0; e < 4; e++) {
            float x0, x1, y0, y1;
            unpack2f(ap0[g * 4 + e], x0, x1);
            unpack2f(ap1[g * 4 + e], y0, y1);
            float o00 = x0 * r0, o01 = x1 * r0;
            float o10 = y0 * r1, o11 = y1 * r1;
            hv0[2 * e] = __float2bfloat16(o00);
            lv0[2 * e] = __float2bfloat16(o00 - __bfloat162float(hv0[2 * e]));
            hv0[2 * e + 1] = __float2bfloat16(o01);
            lv0[2 * e + 1] = __float2bfloat16(o01 - __bfloat162float(hv0[2 * e + 1]));
            hv1[2 * e] = __float2bfloat16(o10);
            lv1[2 * e] = __float2bfloat16(o10 - __bfloat162float(hv1[2 * e]));
            hv1[2 * e + 1] = __float2bfloat16(o11);
            lv1[2 * e + 1] = __float2bfloat16(o11 - __bfloat162float(hv1[2 * e + 1]));
        }
        *(uint4*)(ohi + base + (size_t)q0 * D_MODEL + g * 8) = *(uint4*)hv0;
        *(uint4*)(olo + base + (size_t)q0 * D_MODEL + g * 8) = *(uint4*)lv0;
        *(uint4*)(ohi + base + (size_t)q1 * D_MODEL + g * 8) = *(uint4*)hv1;
        *(uint4*)(olo + base + (size_t)q1 * D_MODEL + g * 8) = *(uint4*)lv1;
    }
}

// ---------------------------------------------------------------------------
extern "C" void kernel_launch(void* const* d_in, const int* in_sizes, int n_in,
                              void* d_out, int out_size)
{
    const float* x  = (const float*)d_in[0];
    const float* Wq = (const float*)d_in[1];
    const float* Wk = (const float*)d_in[2];
    const float* Wv = (const float*)d_in[3];
    const float* Wo = (const float*)d_in[4];
    float* out = (float*)d_out;

    float *q, *k, *v;
    __nv_bfloat16 *x_hi, *x_lo, *att_hi, *att_lo, *wt_hi, *wt_lo;
    cudaGetSymbolAddress((void**)&q, g_q);
    cudaGetSymbolAddress((void**)&k, g_k);
    cudaGetSymbolAddress((void**)&v, g_v);
    cudaGetSymbolAddress((void**)&x_hi, g_x_hi);
    cudaGetSymbolAddress((void**)&x_lo, g_x_lo);
    cudaGetSymbolAddress((void**)&att_hi, g_att_hi);
    cudaGetSymbolAddress((void**)&att_lo, g_att_lo);
    cudaGetSymbolAddress((void**)&wt_hi, g_wt_hi);
    cudaGetSymbolAddress((void**)&wt_lo, g_wt_lo);

    cudaFuncSetAttribute(gemm_mma_kernel,
                         cudaFuncAttributeMaxDynamicSharedMemorySize, GEMM_SMEM);
    cudaFuncSetAttribute(attn_kernel,
                         cudaFuncAttributeMaxDynamicSharedMemorySize, ATT_SMEM_BYTES);

    const size_t DD = (size_t)D_MODEL * D_MODEL;
    const int n4 = ROWS * D_MODEL / 4;
    dim3 wgrid(32, 32), wblk(32, 8);
    dim3 gg(D_MODEL / 128, ROWS / 128);   // (8, 256)

    // launches 1-5: conversions (ncu -s 5 -c 1 captures launch #6 = gemm Q)
    split_kernel<<<(n4 + 255) / 256, 256>>>(x, x_hi, x_lo, n4);
    wsplit_kernel<<<wgrid, wblk>>>(Wq, wt_hi + 0 * DD, wt_lo + 0 * DD);
    wsplit_kernel<<<wgrid, wblk>>>(Wk, wt_hi + 1 * DD, wt_lo + 1 * DD);
    wsplit_kernel<<<wgrid, wblk>>>(Wv, wt_hi + 2 * DD, wt_lo + 2 * DD);
    wsplit_kernel<<<wgrid, wblk>>>(Wo, wt_hi + 3 * DD, wt_lo + 3 * DD);

    // launch 6: gemm Q (profiled)
    gemm_mma_kernel<<<gg, 256, GEMM_SMEM>>>(x_hi, x_lo, wt_hi + 0 * DD, wt_lo + 0 * DD, q);
    gemm_mma_kernel<<<gg, 256, GEMM_SMEM>>>(x_hi, x_lo, wt_hi + 1 * DD, wt_lo + 1 * DD, k);
    gemm_mma_kernel<<<gg, 256, GEMM_SMEM>>>(x_hi, x_lo, wt_hi + 2 * DD, wt_lo + 2 * DD, v);

    // attention (128 threads, 2 queries/thread, f32x2 math)
    dim3 attn_grid(NH, NCHUNK, BATCH);
    attn_kernel<<<attn_grid, 128, ATT_SMEM_BYTES>>>(q, k, v, att_hi, att_lo);

    // output projection
    gemm_mma_kernel<<<gg, 256, GEMM_SMEM>>>(att_hi, att_lo, wt_hi + 3 * DD, wt_lo + 3 * DD, out);
}

// round 8
// speedup vs baseline: 3.2161x; 1.0041x over previous
#include <cuda_runtime.h>
#include <cuda_bf16.h>
#include <cstdint>

#define D_MODEL 1024
#define NH 16
#define HD 64
#define CHUNK 256
#define WIN 64
#define BATCH 4
#define SEQ 8192
#define NCHUNK (SEQ / CHUNK)
#define ROWS (BATCH * SEQ)

// ---------------- scratch (__device__ globals; no allocs allowed) ----------
__device__ float g_q[ROWS * D_MODEL];
__device__ float g_k[ROWS * D_MODEL];
__device__ float g_v[ROWS * D_MODEL];
__device__ __nv_bfloat16 g_x_hi[ROWS * D_MODEL];
__device__ __nv_bfloat16 g_x_lo[ROWS * D_MODEL];
__device__ __nv_bfloat16 g_att_hi[ROWS * D_MODEL];
__device__ __nv_bfloat16 g_att_lo[ROWS * D_MODEL];
// 4 transposed weights (q,k,v,o), hi/lo limbs, each [N=1024][K=1024] (K-major)
__device__ __nv_bfloat16 g_wt_hi[4 * D_MODEL * D_MODEL];
__device__ __nv_bfloat16 g_wt_lo[4 * D_MODEL * D_MODEL];

// ---------------------------------------------------------------------------
// helpers
// ---------------------------------------------------------------------------
__device__ __forceinline__ uint32_t smem_u32(const void* p) {
    uint32_t a;
    asm("{ .reg .u64 t; cvta.to.shared.u64 t, %1; cvt.u32.u64 %0, t; }"
        : "=r"(a) : "l"(p));
    return a;
}

__device__ __forceinline__ void cp_async16(uint32_t dst, const void* src) {
    asm volatile("cp.async.cg.shared.global [%0], [%1], 16;"
                 :: "r"(dst), "l"(src) : "memory");
}
__device__ __forceinline__ void cp_commit() {
    asm volatile("cp.async.commit_group;" ::: "memory");
}
__device__ __forceinline__ void cp_wait1() {
    asm volatile("cp.async.wait_group 1;" ::: "memory");
}

__device__ __forceinline__ void ldsm_x4(uint32_t* r, uint32_t addr) {
    asm volatile("ldmatrix.sync.aligned.m8n8.x4.shared.b16 {%0,%1,%2,%3}, [%4];"
                 : "=r"(r[0]), "=r"(r[1]), "=r"(r[2]), "=r"(r[3]) : "r"(addr));
}

__device__ __forceinline__ void mma16816(float* c, const uint32_t* a, const uint32_t* b) {
    asm volatile(
        "mma.sync.aligned.m16n8k16.row.col.f32.bf16.bf16.f32 "
        "{%0,%1,%2,%3}, {%4,%5,%6,%7}, {%8,%9}, {%0,%1,%2,%3};"
        : "+f"(c[0]), "+f"(c[1]), "+f"(c[2]), "+f"(c[3])
        : "r"(a[0]), "r"(a[1]), "r"(a[2]), "r"(a[3]), "r"(b[0]), "r"(b[1]));
}

// ---- packed f32x2 ops (FFMA2 path, PTX-only per SASS_QUICKREF) ----
__device__ __forceinline__ uint64_t pack2f(float lo, float hi) {
    uint64_t r;
    asm("mov.b64 %0, {%1,%2};" : "=l"(r) : "f"(lo), "f"(hi));
    return r;
}
__device__ __forceinline__ void unpack2f(uint64_t p, float& lo, float& hi) {
    asm("mov.b64 {%0,%1}, %2;" : "=f"(lo), "=f"(hi) : "l"(p));
}
__device__ __forceinline__ void fma2(uint64_t& d, uint64_t a, uint64_t b) {
    asm("fma.rn.f32x2 %0, %1, %2, %0;" : "+l"(d) : "l"(a), "l"(b));
}
__device__ __forceinline__ uint64_t mul2(uint64_t a, uint64_t b) {
    uint64_t r;
    asm("mul.rn.f32x2 %0, %1, %2;" : "=l"(r) : "l"(a), "l"(b));
    return r;
}
__device__ __forceinline__ uint64_t add2(uint64_t a, uint64_t b) {
    uint64_t r;
    asm("add.rn.f32x2 %0, %1, %2;" : "=l"(r) : "l"(a), "l"(b));
    return r;
}
__device__ __forceinline__ void lds_v2u64(uint64_t& a, uint64_t& b, uint32_t addr) {
    asm volatile("ld.shared.v2.b64 {%0,%1}, [%2];" : "=l"(a), "=l"(b) : "r"(addr));
}

// tile geometry: 128 rows x 32 bf16 cols = 64B rows, 4x 16B chunks per row
// swizzled 16B-chunk: c' = c ^ ((r>>1)&3)
#define TILE_B 8192
#define STAGE_B (4 * TILE_B)   // Ahi, Alo, Bhi, Blo
#define NSTAGE 3
#define GEMM_SMEM (NSTAGE * STAGE_B)  // 98304
#define KIT 32                 // 1024 / 32

__device__ __forceinline__ uint32_t sw_addr(uint32_t tile_base, int r, int c) {
    return tile_base + r * 64 + ((c ^ ((r >> 1) & 3)) << 4);
}

// ---------------------------------------------------------------------------
// Split fp32 -> bf16 hi/lo limbs
// ---------------------------------------------------------------------------
__global__ __launch_bounds__(256) void split_kernel(
    const float* __restrict__ in, __nv_bfloat16* __restrict__ hi,
    __nv_bfloat16* __restrict__ lo, int n4)
{
    int i = blockIdx.x * blockDim.x + threadIdx.x;
    if (i >= n4) return;
    float4 x = ((const float4*)in)[i];
    float v[4] = {x.x, x.y, x.z, x.w};
    __nv_bfloat16 h[4], l[4];
#pragma unroll
    for (int j = 0; j < 4; j++) {
        h[j] = __float2bfloat16(v[j]);
        l[j] = __float2bfloat16(v[j] - __bfloat162float(h[j]));
    }
    *(uint2*)(hi + 4 * (size_t)i) = *(uint2*)h;
    *(uint2*)(lo + 4 * (size_t)i) = *(uint2*)l;
}

// Fused weight transpose + split for all 4 weights (grid.z selects W)
__global__ __launch_bounds__(256) void wsplit4_kernel(
    const float* __restrict__ W0, const float* __restrict__ W1,
    const float* __restrict__ W2, const float* __restrict__ W3,
    __nv_bfloat16* __restrict__ hiT, __nv_bfloat16* __restrict__ loT)
{
    __shared__ float tile[32][33];
    const int z = blockIdx.z;
    const float* W = (z == 0) ? W0 : (z == 1) ? W1 : (z == 2) ? W2 : W3;
    const size_t off = (size_t)z * D_MODEL * D_MODEL;
    int bx = blockIdx.x * 32, by = blockIdx.y * 32;
    int tx = threadIdx.x, ty = threadIdx.y;  // 32x8
#pragma unroll
    for (int r = ty; r < 32; r += 8)
        tile[r][tx] = W[(size_t)(by + r) * D_MODEL + bx + tx];
    __syncthreads();
#pragma unroll
    for (int r = ty; r < 32; r += 8) {
        float v = tile[tx][r];  // = W[(by+tx)*D + bx+r]
        __nv_bfloat16 h = __float2bfloat16(v);
        size_t o = off + (size_t)(bx + r) * D_MODEL + by + tx;
        hiT[o] = h;
        loT[o] = __float2bfloat16(v - __bfloat162float(h));
    }
}

// ---------------------------------------------------------------------------
// bf16-split GEMM via mma.sync: C[M,1024] = (Ahi+Alo) @ (Bhi+Blo)^T, fp32 acc
// CTA 128x128, BK=32, 3-stage cp.async pipeline, 8 warps (2m x 4n),
// 2 CTAs/SM. Single barrier per mainloop iteration.
// ---------------------------------------------------------------------------
__global__ __launch_bounds__(256, 2) void gemm_mma_kernel(
    const __nv_bfloat16* __restrict__ Ahi, const __nv_bfloat16* __restrict__ Alo,
    const __nv_bfloat16* __restrict__ Bhi, const __nv_bfloat16* __restrict__ Blo,
    float* __restrict__ C)
{
    extern __shared__ char smem[];
    const uint32_t sbase = smem_u32(smem);
    const int tid = threadIdx.x;
    const int lane = tid & 31;
    const int wid = tid >> 5;
    const int wm = wid >> 2;        // 0..1
    const int wn = wid & 3;         // 0..3
    const int m0 = blockIdx.y * 128;
    const int n0 = blockIdx.x * 128;

    const __nv_bfloat16* srcs[4] = {Ahi, Alo, Bhi, Blo};

    auto load_stage = [&](int stage, int k0) {
        uint32_t sb = sbase + stage * STAGE_B;
#pragma unroll
        for (int t = 0; t < 4; t++) {
            int row0 = (t < 2) ? m0 : n0;
            const __nv_bfloat16* s = srcs[t];
#pragma unroll
            for (int i = 0; i < 2; i++) {
                int cid = tid + i * 256;       // 0..511
                int r = cid >> 2;
                int c = cid & 3;
                const void* g = s + (size_t)(row0 + r) * D_MODEL + k0 + c * 8;
                cp_async16(sw_addr(sb + t * TILE_B, r, c), g);
            }
        }
    };

    float acc[4][4][4];
#pragma unroll
    for (int i = 0; i < 4; i++)
#pragma unroll
        for (int j = 0; j < 4; j++)
#pragma unroll
            for (int e = 0; e < 4; e++) acc[i][j][e] = 0.f;

    load_stage(0, 0);
    cp_commit();
    load_stage(1, 32);
    cp_commit();

    const int a_r = lane & 15;
    const int a_c = lane >> 4;
    const int b_r = (lane & 7) + ((lane >> 4) << 3);
    const int b_c = (lane >> 3) & 1;

    for (int it = 0; it < KIT; it++) {
        cp_wait1();
        __syncthreads();
        if (it + 2 < KIT) load_stage((it + 2) % NSTAGE, (it + 2) * 32);
        cp_commit();

        const uint32_t sb = sbase + (it % NSTAGE) * STAGE_B;
        const uint32_t tAhi = sb;
        const uint32_t tAlo = sb + TILE_B;
        const uint32_t tBhi = sb + 2 * TILE_B;
        const uint32_t tBlo = sb + 3 * TILE_B;

#pragma unroll
        for (int ks = 0; ks < 2; ks++) {
            uint32_t a[4][4], bh[4][2], bl[4][2];
#pragma unroll
            for (int mt = 0; mt < 4; mt++) {
                int r = wm * 64 + mt * 16 + a_r;
                ldsm_x4(a[mt], sw_addr(tAhi, r, ks * 2 + a_c));
            }
#pragma unroll
            for (int np = 0; np < 2; np++) {
                uint32_t t4[4];
                int r = wn * 32 + np * 16 + b_r;
                ldsm_x4(t4, sw_addr(tBhi, r, ks * 2 + b_c));
                bh[np * 2][0] = t4[0]; bh[np * 2][1] = t4[1];
                bh[np * 2 + 1][0] = t4[2]; bh[np * 2 + 1][1] = t4[3];
            }
#pragma unroll
            for (int np = 0; np < 2; np++) {
                uint32_t t4[4];
                int r = wn * 32 + np * 16 + b_r;
                ldsm_x4(t4, sw_addr(tBlo, r, ks * 2 + b_c));
                bl[np * 2][0] = t4[0]; bl[np * 2][1] = t4[1];
                bl[np * 2 + 1][0] = t4[2]; bl[np * 2 + 1][1] = t4[3];
            }
#pragma unroll
            for (int mt = 0; mt < 4; mt++)
#pragma unroll
                for (int nt = 0; nt < 4; nt++)
                    mma16816(acc[mt][nt], a[mt], bh[nt]);
#pragma unroll
            for (int mt = 0; mt < 4; mt++)
#pragma unroll
                for (int nt = 0; nt < 4; nt++)
                    mma16816(acc[mt][nt], a[mt], bl[nt]);
#pragma unroll
            for (int mt = 0; mt < 4; mt++) {
                int r = wm * 64 + mt * 16 + a_r;
                ldsm_x4(a[mt], sw_addr(tAlo, r, ks * 2 + a_c));
            }
#pragma unroll
            for (int mt = 0; mt < 4; mt++)
#pragma unroll
                for (int nt = 0; nt < 4; nt++)
                    mma16816(acc[mt][nt], a[mt], bh[nt]);
        }
    }

    const int er = lane >> 2;
    const int ec = (lane & 3) * 2;
#pragma unroll
    for (int mt = 0; mt < 4; mt++) {
#pragma unroll
        for (int nt = 0; nt < 4; nt++) {
            int row = m0 + wm * 64 + mt * 16 + er;
            int col = n0 + wn * 32 + nt * 8 + ec;
            *(float2*)(C + (size_t)row * D_MODEL + col) =
                make_float2(acc[mt][nt][0], acc[mt][nt][1]);
            *(float2*)(C + (size_t)(row + 8) * D_MODEL + col) =
                make_float2(acc[mt][nt][2], acc[mt][nt][3]);
        }
    }
}

// ---------------------------------------------------------------------------
// Banded chunk-local attention: 128 threads/CTA, 2 adjacent queries/thread,
// f32x2 math, FOUR independent accumulation chains per query in the score
// pass (chain depth 16, matches issue rate at 1 warp/SMSP).
// ---------------------------------------------------------------------------
#define ATT_SC 66
#define ATT_SMEM_BYTES ((CHUNK * 64 + CHUNK * ATT_SC) * 4)  // 133120

__device__ __forceinline__ int att_addr(int r, int c) {  // float index, c = 16B chunk
    return r * 64 + ((c ^ ((r >> 1) & 7)) << 2);
}

__device__ __forceinline__ void att_load_tile(
    float* __restrict__ buf, const float* __restrict__ src, size_t base, int tid)
{
#pragma unroll
    for (int i = 0; i < 32; i++) {
        int idx = tid + i * 128;          // 0..4095
        int r = idx >> 4;
        int c = idx & 15;
        float4 t = *(const float4*)(src + base + (size_t)r * D_MODEL + c * 4);
        *(float4*)(buf + att_addr(r, c)) = t;
    }
}

__global__ __launch_bounds__(128) void attn_kernel(
    const float* __restrict__ q, const float* __restrict__ k,
    const float* __restrict__ v,
    __nv_bfloat16* __restrict__ ohi, __nv_bfloat16* __restrict__ olo)
{
    extern __shared__ float fsmem[];
    float* buf = fsmem;                      // [256][64] swizzled
    float* sc  = fsmem + CHUNK * 64;         // [256][66]
    const uint32_t sb = smem_u32(fsmem);

    const int h = blockIdx.x;
    const int n = blockIdx.y;
    const int b = blockIdx.z;
    const int t = threadIdx.x;               // 0..127
    const int q0 = 2 * t;
    const int q1 = 2 * t + 1;

    const size_t base = ((size_t)(b * SEQ + n * CHUNK)) * D_MODEL + h * HD;

    // ---- stage q, pull both rows into packed registers (pre-scaled) ----
    att_load_tile(buf, q, base, t);
    __syncthreads();
    uint64_t qp0[32], qp1[32];
    {
        const uint64_t scale2 = pack2f(0.125f, 0.125f);
#pragma unroll
        for (int c = 0; c < 16; c++) {
            uint64_t a, bq;
            lds_v2u64(a, bq, sb + 4 * att_addr(q0, c));
            qp0[2 * c] = mul2(a, scale2); qp0[2 * c + 1] = mul2(bq, scale2);
            lds_v2u64(a, bq, sb + 4 * att_addr(q1, c));
            qp1[2 * c] = mul2(a, scale2); qp1[2 * c + 1] = mul2(bq, scale2);
        }
    }
    __syncthreads();

    // ---- k tile ----
    att_load_tile(buf, k, base, t);
    __syncthreads();

    // ---- scores over the band; 4 chains per query pair ----
    const uint64_t zero2 = pack2f(0.f, 0.f);
    float m0 = -1e30f, m1 = -1e30f;
#pragma unroll 2
    for (int ju = 0; ju <= 65; ju++) {
        int j = q0 - 64 + ju;                 // key row
        float s0 = -1e30f, s1 = -1e30f;
        if (j >= 0) {
            uint64_t a0a = zero2, a0b = zero2, a1a = zero2, a1b = zero2;
#pragma unroll
            for (int c = 0; c < 16; c += 2) {   // 2 chunks = 8 floats per step
                uint64_t k0, k1, k2, k3;
                lds_v2u64(k0, k1, sb + 4 * att_addr(j, c));
                lds_v2u64(k2, k3, sb + 4 * att_addr(j, c + 1));
                fma2(a0a, qp0[2 * c], k0);     fma2(a1a, qp1[2 * c], k0);
                fma2(a0b, qp0[2 * c + 1], k1); fma2(a1b, qp1[2 * c + 1], k1);
                fma2(a0a, qp0[2 * c + 2], k2); fma2(a1a, qp1[2 * c + 2], k2);
                fma2(a0b, qp0[2 * c + 3], k3); fma2(a1b, qp1[2 * c + 3], k3);
            }
            uint64_t t0 = add2(a0a, a0b);
            uint64_t t1 = add2(a1a, a1b);
            float e0, o0, e1, o1;
            unpack2f(t0, e0, o0);
            unpack2f(t1, e1, o1);
            if (ju <= 64) { s0 = e0 + o0; m0 = fmaxf(m0, s0); }
            if (ju >= 1)  { s1 = e1 + o1; m1 = fmaxf(m1, s1); }
        }
        sc[q0 * ATT_SC + ju] = s0;
        sc[q1 * ATT_SC + ju] = s1;
    }

    // ---- softmax (sentinel -1e30 -> exp underflows to 0) ----
    float l0a = 0.f, l0b = 0.f, l1a = 0.f, l1b = 0.f;
#pragma unroll 2
    for (int ju = 0; ju <= 65; ju += 2) {
        float p00 = __expf(sc[q0 * ATT_SC + ju] - m0);
        float p01 = __expf(sc[q0 * ATT_SC + ju + 1] - m0);
        float p10 = __expf(sc[q1 * ATT_SC + ju] - m1);
        float p11 = __expf(sc[q1 * ATT_SC + ju + 1] - m1);
        l0a += p00; l0b += p01; l1a += p10; l1b += p11;
        sc[q0 * ATT_SC + ju] = p00;
        sc[q0 * ATT_SC + ju + 1] = p01;
        sc[q1 * ATT_SC + ju] = p10;
        sc[q1 * ATT_SC + ju + 1] = p11;
    }
    const float l0 = l0a + l0b;
    const float l1 = l1a + l1b;
    __syncthreads();

    // ---- v tile (reuse buf) ----
    att_load_tile(buf, v, base, t);
    __syncthreads();

    // ---- P @ V; packed accumulators over dim pairs (independent chains) ----
    uint64_t ap0[32], ap1[32];
#pragma unroll
    for (int i = 0; i < 32; i++) { ap0[i] = zero2; ap1[i] = zero2; }
#pragma unroll 2
    for (int ju = 0; ju <= 65; ju++) {
        int j = q0 - 64 + ju;
        if (j >= 0) {
            float p0 = sc[q0 * ATT_SC + ju];
            float p1 = sc[q1 * ATT_SC + ju];
            uint64_t pp0 = pack2f(p0, p0);
            uint64_t pp1 = pack2f(p1, p1);
#pragma unroll
            for (int c = 0; c < 16; c += 2) {
                uint64_t v0, v1, v2, v3;
                lds_v2u64(v0, v1, sb + 4 * att_addr(j, c));
                lds_v2u64(v2, v3, sb + 4 * att_addr(j, c + 1));
                fma2(ap0[2 * c], pp0, v0);     fma2(ap1[2 * c], pp1, v0);
                fma2(ap0[2 * c + 1], pp0, v1); fma2(ap1[2 * c + 1], pp1, v1);
                fma2(ap0[2 * c + 2], pp0, v2); fma2(ap1[2 * c + 2], pp1, v2);
                fma2(ap0[2 * c + 3], pp0, v3); fma2(ap1[2 * c + 3], pp1, v3);
            }
        }
    }
    const float r0 = 1.f / l0;
    const float r1 = 1.f / l1;

    // ---- fused bf16 hi/lo split, direct 16B stores (2 rows) ----
#pragma unroll
    for (int g = 0; g < 8; g++) {          // 8 dims per group = 4 packed pairs
        __nv_bfloat16 hv0[8], lv0[8], hv1[8], lv1[8];
#pragma unroll
        for (int e = 0; e < 4; e++) {
            float x0, x1, y0, y1;
            unpack2f(ap0[g * 4 + e], x0, x1);
            unpack2f(ap1[g * 4 + e], y0, y1);
            float o00 = x0 * r0, o01 = x1 * r0;
            float o10 = y0 * r1, o11 = y1 * r1;
            hv0[2 * e] = __float2bfloat16(o00);
            lv0[2 * e] = __float2bfloat16(o00 - __bfloat162float(hv0[2 * e]));
            hv0[2 * e + 1] = __float2bfloat16(o01);
            lv0[2 * e + 1] = __float2bfloat16(o01 - __bfloat162float(hv0[2 * e + 1]));
            hv1[2 * e] = __float2bfloat16(o10);
            lv1[2 * e] = __float2bfloat16(o10 - __bfloat162float(hv1[2 * e]));
            hv1[2 * e + 1] = __float2bfloat16(o11);
            lv1[2 * e + 1] = __float2bfloat16(o11 - __bfloat162float(hv1[2 * e + 1]));
        }
        *(uint4*)(ohi + base + (size_t)q0 * D_MODEL + g * 8) = *(uint4*)hv0;
        *(uint4*)(olo + base + (size_t)q0 * D_MODEL + g * 8) = *(uint4*)lv0;
        *(uint4*)(ohi + base + (size_t)q1 * D_MODEL + g * 8) = *(uint4*)hv1;
        *(uint4*)(olo + base + (size_t)q1 * D_MODEL + g * 8) = *(uint4*)lv1;
    }
}

// ---------------------------------------------------------------------------
extern "C" void kernel_launch(void* const* d_in, const int* in_sizes, int n_in,
                              void* d_out, int out_size)
{
    const float* x  = (const float*)d_in[0];
    const float* Wq = (const float*)d_in[1];
    const float* Wk = (const float*)d_in[2];
    const float* Wv = (const float*)d_in[3];
    const float* Wo = (const float*)d_in[4];
    float* out = (float*)d_out;

    float *q, *k, *v;
    __nv_bfloat16 *x_hi, *x_lo, *att_hi, *att_lo, *wt_hi, *wt_lo;
    cudaGetSymbolAddress((void**)&q, g_q);
    cudaGetSymbolAddress((void**)&k, g_k);
    cudaGetSymbolAddress((void**)&v, g_v);
    cudaGetSymbolAddress((void**)&x_hi, g_x_hi);
    cudaGetSymbolAddress((void**)&x_lo, g_x_lo);
    cudaGetSymbolAddress((void**)&att_hi, g_att_hi);
    cudaGetSymbolAddress((void**)&att_lo, g_att_lo);
    cudaGetSymbolAddress((void**)&wt_hi, g_wt_hi);
    cudaGetSymbolAddress((void**)&wt_lo, g_wt_lo);

    cudaFuncSetAttribute(gemm_mma_kernel,
                         cudaFuncAttributeMaxDynamicSharedMemorySize, GEMM_SMEM);
    cudaFuncSetAttribute(attn_kernel,
                         cudaFuncAttributeMaxDynamicSharedMemorySize, ATT_SMEM_BYTES);

    const size_t DD = (size_t)D_MODEL * D_MODEL;
    const int n4 = ROWS * D_MODEL / 4;
    dim3 gg(D_MODEL / 128, ROWS / 128);   // (8, 256)

    // conversions: input split + fused 4-weight transpose/split
    split_kernel<<<(n4 + 255) / 256, 256>>>(x, x_hi, x_lo, n4);
    dim3 wgrid(32, 32, 4), wblk(32, 8);
    wsplit4_kernel<<<wgrid, wblk>>>(Wq, Wk, Wv, Wo, wt_hi, wt_lo);

    // QKV projections on tensor cores (mma.sync)
    gemm_mma_kernel<<<gg, 256, GEMM_SMEM>>>(x_hi, x_lo, wt_hi + 0 * DD, wt_lo + 0 * DD, q);
    gemm_mma_kernel<<<gg, 256, GEMM_SMEM>>>(x_hi, x_lo, wt_hi + 1 * DD, wt_lo + 1 * DD, k);
    gemm_mma_kernel<<<gg, 256, GEMM_SMEM>>>(x_hi, x_lo, wt_hi + 2 * DD, wt_lo + 2 * DD, v);

    // attention (128 threads, 2 queries/thread, multi-chain f32x2 math)
    dim3 attn_grid(NH, NCHUNK, BATCH);
    attn_kernel<<<attn_grid, 128, ATT_SMEM_BYTES>>>(q, k, v, att_hi, att_lo);

    // output projection
    gemm_mma_kernel<<<gg, 256, GEMM_SMEM>>>(att_hi, att_lo, wt_hi + 3 * DD, wt_lo + 3 * DD, out);
}